// round 14
// baseline (speedup 1.0000x reference)
#include <cuda_runtime.h>
#include <math.h>
#include <stdint.h>

#define N_TOK   8192
#define DMODEL  512
#define NEXP    8
#define HID     1024
#define RHID    256
#define INDIM   4611
#define XLD     4624
#define KP4     1160
#define NROWS   (N_TOK * 2)
#define LN_EPS  1e-5f
#define QMAXF   16256.0f

#define TM 128
#define TN 64
#define TK 16
#define SM_B0   32768u
#define SM_ROW  (32768u + 3u * 4096u)
#define SMEM_TOTAL (45056 + 512)

typedef unsigned long long u64;

__device__ __align__(16) float g_x[(size_t)N_TOK * XLD];
__device__ __align__(16) float g_zres[(size_t)N_TOK * DMODEL];
__device__ __align__(16) float g_rh[(size_t)N_TOK * RHID];
__device__ float g_topw[N_TOK * 2];
__device__ int   g_topi[N_TOK * 2];
__device__ int   g_cnt[NEXP];
__device__ int   g_off[NEXP + 1];
__device__ int   g_cursor[NEXP];
__device__ int   g_rows_token[NROWS];
__device__ int   g_rows_slot[NROWS];
__device__ float g_rows_w[NROWS];
__device__ __align__(16) float g_eh[(size_t)NROWS * HID];
__device__ __align__(16) float g_outs[(size_t)NROWS * DMODEL];
__device__ __align__(16) uint32_t g_xq1[(size_t)N_TOK * KP4];
__device__ __align__(16) uint32_t g_xq0[(size_t)N_TOK * KP4];
__device__ __align__(16) uint32_t g_wq1[(size_t)NEXP * KP4 * HID];
__device__ __align__(16) uint32_t g_wq0[(size_t)NEXP * KP4 * HID];
__device__ float    g_sa[N_TOK];
__device__ float    g_sw[NEXP * HID];
__device__ unsigned g_swmax[NEXP * HID];

__device__ __forceinline__ uint32_t smem_u32(const void* p) {
    uint32_t a;
    asm("{ .reg .u64 t; cvta.to.shared.u64 t, %1; cvt.u32.u64 %0, t; }" : "=r"(a) : "l"(p));
    return a;
}
#define FMA2(acc, a, b) asm("fma.rn.f32x2 %0, %1, %2, %0;" : "+l"(acc) : "l"(a), "l"(b))
#define PACKDUP(d, f) do { unsigned _u = __float_as_uint(f); \
    asm("mov.b64 %0, {%1, %2};" : "=l"(d) : "r"(_u), "r"(_u)); } while (0)
#define UNPACK2(lo, hi, v) do { unsigned _a, _b; \
    asm("mov.b64 {%0, %1}, %2;" : "=r"(_a), "=r"(_b) : "l"(v)); \
    lo = __uint_as_float(_a); hi = __uint_as_float(_b); } while (0)
__device__ __forceinline__ void cp16sz(uint32_t dst, const void* src, uint32_t sz) {
    asm volatile("cp.async.cg.shared.global [%0], [%1], 16, %2;" :: "r"(dst), "l"(src), "r"(sz) : "memory");
}
__device__ __forceinline__ void cp16(uint32_t dst, const void* src) {
    asm volatile("cp.async.cg.shared.global [%0], [%1], 16;" :: "r"(dst), "l"(src) : "memory");
}
#define CP_COMMIT() asm volatile("cp.async.commit_group;" ::: "memory")
#define CP_WAIT(n)  asm volatile("cp.async.wait_group %0;" :: "n"(n) : "memory")

__device__ __forceinline__ float gelu_f(float v) {
    return 0.5f * v * (1.0f + erff(v * 0.70710678118654752440f));
}
__device__ __forceinline__ void qsplit(float v, float inv, int& h, int& l) {
    int q = __float2int_rn(v * inv);
    h = (q + 64) >> 7;
    l = q - (h << 7);
}

template<int NV>
__device__ __forceinline__ void blockReduceV(float* v, float* sbuf) {
    int lane = threadIdx.x & 31, w = threadIdx.x >> 5;
    #pragma unroll
    for (int n = 0; n < NV; n++)
        #pragma unroll
        for (int o = 16; o; o >>= 1)
            v[n] += __shfl_xor_sync(0xffffffffu, v[n], o);
    if (lane == 0)
        #pragma unroll
        for (int n = 0; n < NV; n++) sbuf[w * NV + n] = v[n];
    __syncthreads();
    if (w == 0) {
        float a[NV];
        #pragma unroll
        for (int n = 0; n < NV; n++) {
            a[n] = (lane < 8) ? sbuf[lane * NV + n] : 0.f;
            #pragma unroll
            for (int o = 4; o; o >>= 1)
                a[n] += __shfl_xor_sync(0xffffffffu, a[n], o);
        }
        if (lane == 0)
            #pragma unroll
            for (int n = 0; n < NV; n++) sbuf[n] = a[n];
    }
    __syncthreads();
    #pragma unroll
    for (int n = 0; n < NV; n++) v[n] = sbuf[n];
    __syncthreads();
}

// ---------- build_x (blocks < N_TOK) fused with wcolmax (blocks >= N_TOK) ---
__global__ __launch_bounds__(256) void build_x_colmax(
    const float* __restrict__ z1, const float* __restrict__ z2,
    const float* __restrict__ z3, const float* __restrict__ mask,
    const float* __restrict__ ln_g, const float* __restrict__ ln_b,
    const float* __restrict__ lnp_g, const float* __restrict__ lnp_b,
    const float* __restrict__ e_w1)
{
    if (blockIdx.x >= N_TOK) {
        // wcolmax branch: 928 blocks = 29 ks-chunks x 8 experts x 4 col-chunks
        int id = blockIdx.x - N_TOK;
        int ks = id / 32, rem = id % 32;
        int e = rem >> 2, nx = rem & 3;
        int n = nx * 256 + threadIdx.x;
        int k0 = ks * 159, k1 = min(INDIM, k0 + 159);
        const float* W = e_w1 + (size_t)e * INDIM * HID + n;
        float mx = 0.f;
        #pragma unroll 4
        for (int k = k0; k < k1; k++) mx = fmaxf(mx, fabsf(W[(size_t)k * HID]));
        atomicMax(&g_swmax[e * HID + n], __float_as_uint(mx));
        return;
    }

    int n = blockIdx.x, t = threadIdx.x;
    __shared__ float a1[DMODEL], a2[DMODEL], a3[DMODEL];
    __shared__ float red[8 * 12];
    size_t zb = (size_t)n * DMODEL;
    int c0 = 2 * t, c1 = 2 * t + 1;

    float2 x1 = *(const float2*)(z1 + zb + c0);
    float2 x2 = *(const float2*)(z2 + zb + c0);
    float2 x3 = *(const float2*)(z3 + zb + c0);
    float2 gg = *(const float2*)(ln_g + c0);
    float2 bb = *(const float2*)(ln_b + c0);

    float v6[6] = {x1.x + x1.y, x1.x * x1.x + x1.y * x1.y,
                   x2.x + x2.y, x2.x * x2.x + x2.y * x2.y,
                   x3.x + x3.y, x3.x * x3.x + x3.y * x3.y};
    blockReduceV<6>(v6, red);

    float m, rs;
    m = v6[0] * (1.f / DMODEL);
    rs = rsqrtf(v6[1] * (1.f / DMODEL) - m * m + LN_EPS);
    float n1a = (x1.x - m) * rs * gg.x + bb.x, n1b = (x1.y - m) * rs * gg.y + bb.y;
    m = v6[2] * (1.f / DMODEL);
    rs = rsqrtf(v6[3] * (1.f / DMODEL) - m * m + LN_EPS);
    float n2a = (x2.x - m) * rs * gg.x + bb.x, n2b = (x2.y - m) * rs * gg.y + bb.y;
    m = v6[4] * (1.f / DMODEL);
    rs = rsqrtf(v6[5] * (1.f / DMODEL) - m * m + LN_EPS);
    float n3a = (x3.x - m) * rs * gg.x + bb.x, n3b = (x3.y - m) * rs * gg.y + bb.y;

    a1[c0] = n1a; a1[c1] = n1b;
    a2[c0] = n2a; a2[c1] = n2b;
    a3[c0] = n3a; a3[c1] = n3b;

    size_t xb = (size_t)n * XLD;
    g_x[xb + c0] = n1a;              g_x[xb + c1] = n1b;
    g_x[xb + 512 + c0] = n2a;        g_x[xb + 512 + c1] = n2b;
    g_x[xb + 1024 + c0] = n3a;       g_x[xb + 1024 + c1] = n3b;
    __syncthreads();

    float2 pg = *(const float2*)(lnp_g + c0);
    float2 pb = *(const float2*)(lnp_b + c0);
    const float* pp[6] = {a1, a1, a2, a1, a1, a2};
    const float* qq[6] = {a2, a3, a3, a2, a3, a3};
    float uv[6][2];
    float v12[12];
    #pragma unroll
    for (int c = 0; c < 6; c++) {
        float u0, u1;
        if (c < 3) { u0 = pp[c][c0] - qq[c][c0]; u1 = pp[c][c1] - qq[c][c1]; }
        else       { u0 = pp[c][c0] * qq[c][c0]; u1 = pp[c][c1] * qq[c][c1]; }
        uv[c][0] = u0; uv[c][1] = u1;
        v12[2 * c] = u0 + u1;
        v12[2 * c + 1] = u0 * u0 + u1 * u1;
    }
    blockReduceV<12>(v12, red);

    float dv[6][2];
    #pragma unroll
    for (int c = 0; c < 6; c++) {
        float md = v12[2 * c] * (1.f / DMODEL);
        float rsd = rsqrtf(v12[2 * c + 1] * (1.f / DMODEL) - md * md + LN_EPS);
        float v0 = (uv[c][0] - md) * rsd * pg.x + pb.x;
        float v1 = (uv[c][1] - md) * rsd * pg.y + pb.y;
        dv[c][0] = v0; dv[c][1] = v1;
        g_x[xb + (size_t)(3 + c) * 512 + c0] = v0;
        g_x[xb + (size_t)(3 + c) * 512 + c1] = v1;
    }

    float m0 = mask[n * 3 + 0], m1m = mask[n * 3 + 1], m2m = mask[n * 3 + 2];
    if (t < 3) g_x[xb + 4608 + t] = mask[n * 3 + t];
    if (t < 13) g_x[xb + 4611 + t] = 0.f;

    float den = fmaxf(m0 + m1m + m2m, 1.f);
    g_zres[zb + c0] = (m0 * n1a + m1m * n2a + m2m * n3a) / den;
    g_zres[zb + c1] = (m0 * n1b + m1m * n2b + m2m * n3b) / den;

    float sv[9][2] = {{n1a, n1b}, {n2a, n2b}, {n3a, n3b},
        {dv[0][0], dv[0][1]}, {dv[1][0], dv[1][1]}, {dv[2][0], dv[2][1]},
        {dv[3][0], dv[3][1]}, {dv[4][0], dv[4][1]}, {dv[5][0], dv[5][1]}};
    float mx = fmaxf(fmaxf(fabsf(m0), fabsf(m1m)), fabsf(m2m));
    #pragma unroll
    for (int c = 0; c < 9; c++)
        mx = fmaxf(mx, fmaxf(fabsf(sv[c][0]), fabsf(sv[c][1])));
    #pragma unroll
    for (int o = 16; o; o >>= 1) mx = fmaxf(mx, __shfl_xor_sync(0xffffffffu, mx, o));
    if ((t & 31) == 0) red[t >> 5] = mx;
    __syncthreads();
    if (t == 0) {
        float v = red[0];
        #pragma unroll
        for (int i = 1; i < 8; i++) v = fmaxf(v, red[i]);
        red[0] = fmaxf(v, 1e-20f);
        g_sa[n] = red[0] * (1.f / QMAXF);
    }
    __syncthreads();
    float inv = QMAXF / red[0];

    #pragma unroll
    for (int c = 0; c < 9; c++) {
        int h0, l0, h1, l1;
        qsplit(sv[c][0], inv, h0, l0);
        qsplit(sv[c][1], inv, h1, l1);
        uint32_t ph = (uint32_t)(h0 & 0xFF) | ((uint32_t)(h1 & 0xFF) << 8);
        uint32_t pl = (uint32_t)(l0 & 0xFF) | ((uint32_t)(l1 & 0xFF) << 8);
        uint32_t oh = __shfl_down_sync(0xffffffffu, ph, 1);
        uint32_t ol = __shfl_down_sync(0xffffffffu, pl, 1);
        if (!(t & 1)) {
            size_t gi = (size_t)n * KP4 + c * 128 + (t >> 1);
            g_xq1[gi] = ph | (oh << 16);
            g_xq0[gi] = pl | (ol << 16);
        }
    }
    if (t == 0) {
        int h0, l0, h1, l1, h2, l2;
        qsplit(m0, inv, h0, l0); qsplit(m1m, inv, h1, l1); qsplit(m2m, inv, h2, l2);
        size_t gi = (size_t)n * KP4 + 1152;
        g_xq1[gi] = (uint32_t)(h0 & 0xFF) | ((uint32_t)(h1 & 0xFF) << 8) | ((uint32_t)(h2 & 0xFF) << 16);
        g_xq0[gi] = (uint32_t)(l0 & 0xFF) | ((uint32_t)(l1 & 0xFF) << 8) | ((uint32_t)(l2 & 0xFF) << 16);
    }
    if (t >= 1 && t < 8) {
        size_t gi = (size_t)n * KP4 + 1152 + t;
        g_xq1[gi] = 0; g_xq0[gi] = 0;
    }
}

// ---------- router fc1 FFMA (blocks < 256) fused with quant_w (rest) --------
__global__ __launch_bounds__(256) void router_plus_quantw(
    const float* __restrict__ W, const float* __restrict__ bias,
    const float* __restrict__ e_w1)
{
    int bid = blockIdx.x;
    int t = threadIdx.x;
    if (bid >= 256) {
        // quant_w branch: 37120 blocks = 4 col-chunks x 1160 k4 x 8 experts
        int id = bid - 256;
        int nx = id & 3, r = id >> 2;
        int k4 = r % KP4, e = r / KP4;
        int n = nx * 256 + t;
        float mxf = fmaxf(__uint_as_float(g_swmax[e * HID + n]), 1e-20f);
        float inv = QMAXF / mxf;
        if (k4 == 0) g_sw[e * HID + n] = mxf * (1.f / QMAXF);
        uint32_t hw = 0, lw = 0;
        const float* Wm = e_w1 + (size_t)e * INDIM * HID + n;
        #pragma unroll
        for (int j = 0; j < 4; j++) {
            int k = 4 * k4 + j;
            float w = (k < INDIM) ? Wm[(size_t)k * HID] : 0.f;
            int h, l;
            qsplit(w, inv, h, l);
            hw |= (uint32_t)(h & 0xFF) << (8 * j);
            lw |= (uint32_t)(l & 0xFF) << (8 * j);
        }
        size_t idx = ((size_t)e * KP4 + k4) * HID + n;
        g_wq1[idx] = hw;
        g_wq0[idx] = lw;
        return;
    }

    // router tile: bid in [0,256): nt from low 2 bits, mt from the rest
    const int BN = RHID, NS = XLD / TK;
    int nt = (bid & 3) * TN;
    int mt = (bid >> 2) * TM;

    extern __shared__ char smem[];
    uint32_t sb = smem_u32(smem);
    u64*      Adup = (u64*)smem;
    uint32_t* Bsm  = (uint32_t*)(smem + SM_B0);

    int ar = t >> 1, kh = (t & 1) * 8;
    const float* aRow = g_x + (size_t)(mt + ar) * XLD + kh;
    int bkr = t >> 4, bch = (t & 15) * 4;
    const float* bRow = W + (size_t)bkr * BN + nt + bch;
    uint32_t bDstBase = sb + SM_B0 + (uint32_t)(bkr * TN + bch) * 4u;

    int tx = t & 15, ty = t >> 4;
    u64 acc[8][2];
    #pragma unroll
    for (int i = 0; i < 8; i++) { acc[i][0] = 0ull; acc[i][1] = 0ull; }

    float4 aR0, aR1;
    aR0 = *(const float4*)(aRow);
    aR1 = *(const float4*)(aRow + 4);
    cp16sz(bDstBase, (bkr < INDIM) ? bRow : W, (bkr < INDIM) ? 16u : 0u);
    CP_COMMIT();
    {
        float v[8] = {aR0.x, aR0.y, aR0.z, aR0.w, aR1.x, aR1.y, aR1.z, aR1.w};
        #pragma unroll
        for (int i = 0; i < 8; i++) { u64 d; PACKDUP(d, v[i]); Adup[(kh + i) * TM + ar] = d; }
    }
    aR0 = *(const float4*)(aRow + TK);
    aR1 = *(const float4*)(aRow + TK + 4);
    {
        int kb = TK + bkr;
        cp16sz(bDstBase + 4096u, (kb < INDIM) ? (bRow + (size_t)TK * BN) : W, (kb < INDIM) ? 16u : 0u);
    }
    CP_COMMIT();

    #pragma unroll 1
    for (int s = 0; s < NS; s++) {
        CP_WAIT(1);
        __syncthreads();
        const u64* Ad = Adup + (size_t)(s & 1) * (TK * TM);
        const uint32_t* Bb = Bsm + (size_t)(s % 3) * (TK * TN);

        #pragma unroll
        for (int k = 0; k < TK; k++) {
            u64 af[8];
            #pragma unroll
            for (int i = 0; i < 4; i++)
                *(ulonglong2*)&af[2 * i] = *(const ulonglong2*)&Ad[k * TM + ty * 8 + 2 * i];
            ulonglong2 bf = *(const ulonglong2*)&Bb[k * TN + tx * 4];
            #pragma unroll
            for (int i = 0; i < 8; i++) {
                FMA2(acc[i][0], af[i], bf.x);
                FMA2(acc[i][1], af[i], bf.y);
            }
        }

        if (s + 1 < NS) {
            u64* Aw = Adup + (size_t)((s + 1) & 1) * (TK * TM);
            float v[8] = {aR0.x, aR0.y, aR0.z, aR0.w, aR1.x, aR1.y, aR1.z, aR1.w};
            #pragma unroll
            for (int i = 0; i < 8; i++) { u64 d; PACKDUP(d, v[i]); Aw[(kh + i) * TM + ar] = d; }
        }
        if (s + 2 < NS) {
            int s2 = s + 2;
            aR0 = *(const float4*)(aRow + s2 * TK);
            aR1 = *(const float4*)(aRow + s2 * TK + 4);
            int kb = s2 * TK + bkr;
            cp16sz(bDstBase + (uint32_t)(s2 % 3) * 4096u,
                   (kb < INDIM) ? (bRow + (size_t)s2 * TK * BN) : W, (kb < INDIM) ? 16u : 0u);
        }
        CP_COMMIT();
    }

    float4 bv = *(const float4*)(bias + nt + tx * 4);
    #pragma unroll
    for (int i = 0; i < 8; i++) {
        int rloc = ty * 8 + i;
        float c0, c1, c2, c3;
        UNPACK2(c0, c1, acc[i][0]);
        UNPACK2(c2, c3, acc[i][1]);
        float4 o = make_float4(gelu_f(c0 + bv.x), gelu_f(c1 + bv.y),
                               gelu_f(c2 + bv.z), gelu_f(c3 + bv.w));
        *(float4*)(g_rh + (size_t)(mt + rloc) * RHID + nt + tx * 4) = o;
    }
}

// ---------- dp4a expert fc1 (round-8/11 verbatim) ----------
__global__ __launch_bounds__(256, 2) void dp4a_fc1(const float* __restrict__ e_b1)
{
    __shared__ uint32_t As[2][2][8][128];
    __shared__ uint32_t Bs[3][2][8][64];
    __shared__ int   rt_s[128];
    __shared__ float sa_s[128];

    int e = blockIdx.z;
    int m_base = g_off[e];
    int M = g_off[e + 1] - m_base;
    int mt = blockIdx.y * 128;
    if (mt >= M) return;
    int Mblk = min(128, M - mt);
    int nt = blockIdx.x * 64;
    int t = threadIdx.x;

    if (t < 128) {
        int mm = mt + t;
        int tok = g_rows_token[m_base + ((mm < M) ? mm : 0)];
        rt_s[t] = tok;
        sa_s[t] = g_sa[tok];
    }
    __syncthreads();

    int ar = t >> 1, kh = (t & 1) * 4;
    const uint32_t* a1p = g_xq1 + (size_t)rt_s[ar] * KP4 + kh;
    const uint32_t* a0p = g_xq0 + (size_t)rt_s[ar] * KP4 + kh;

    int bl = t >> 7, bi_ = t & 127;
    int bk4 = bi_ >> 4, bn4 = (bi_ & 15) * 4;
    const uint32_t* bp = (bl ? g_wq1 : g_wq0) + ((size_t)e * KP4 + bk4) * HID + nt + bn4;
    uint32_t bDst = smem_u32(&Bs[0][bl][bk4][bn4]);

    int tx = t & 15, ty = t >> 4;
    int P11[8][4], Pm[8][4];
    #pragma unroll
    for (int i = 0; i < 8; i++)
        #pragma unroll
        for (int j = 0; j < 4; j++) { P11[i][j] = 0; Pm[i][j] = 0; }

    uint4 aR1, aR0;
    aR1 = *(const uint4*)a1p;
    aR0 = *(const uint4*)a0p;
    cp16(bDst, bp);
    CP_COMMIT();
    {
        uint32_t v1[4] = {aR1.x, aR1.y, aR1.z, aR1.w};
        uint32_t v0[4] = {aR0.x, aR0.y, aR0.z, aR0.w};
        #pragma unroll
        for (int j = 0; j < 4; j++) { As[0][1][kh + j][ar] = v1[j]; As[0][0][kh + j][ar] = v0[j]; }
    }
    aR1 = *(const uint4*)(a1p + 8);
    aR0 = *(const uint4*)(a0p + 8);
    cp16(bDst + 4096u, bp + 8 * HID);
    CP_COMMIT();

    const int NSTG = KP4 / 8;
    #pragma unroll 1
    for (int s = 0; s < NSTG; s++) {
        CP_WAIT(1);
        __syncthreads();
        int ab = s & 1, bb = s % 3;

        #pragma unroll
        for (int k4 = 0; k4 < 8; k4++) {
            uint4 f1a = *(const uint4*)&As[ab][1][k4][ty * 8];
            uint4 f1b = *(const uint4*)&As[ab][1][k4][ty * 8 + 4];
            uint4 f0a = *(const uint4*)&As[ab][0][k4][ty * 8];
            uint4 f0b = *(const uint4*)&As[ab][0][k4][ty * 8 + 4];
            uint4 bw1 = *(const uint4*)&Bs[bb][1][k4][tx * 4];
            uint4 bw0 = *(const uint4*)&Bs[bb][0][k4][tx * 4];
            uint32_t a1v[8] = {f1a.x, f1a.y, f1a.z, f1a.w, f1b.x, f1b.y, f1b.z, f1b.w};
            uint32_t a0v[8] = {f0a.x, f0a.y, f0a.z, f0a.w, f0b.x, f0b.y, f0b.z, f0b.w};
            uint32_t b1v[4] = {bw1.x, bw1.y, bw1.z, bw1.w};
            uint32_t b0v[4] = {bw0.x, bw0.y, bw0.z, bw0.w};
            #pragma unroll
            for (int i = 0; i < 8; i++)
                #pragma unroll
                for (int j = 0; j < 4; j++) {
                    P11[i][j] = __dp4a((int)a1v[i], (int)b1v[j], P11[i][j]);
                    Pm[i][j]  = __dp4a((int)a1v[i], (int)b0v[j], Pm[i][j]);
                    Pm[i][j]  = __dp4a((int)a0v[i], (int)b1v[j], Pm[i][j]);
                }
        }

        if (s + 1 < NSTG) {
            int nb = (s + 1) & 1;
            uint32_t v1[4] = {aR1.x, aR1.y, aR1.z, aR1.w};
            uint32_t v0[4] = {aR0.x, aR0.y, aR0.z, aR0.w};
            #pragma unroll
            for (int j = 0; j < 4; j++) { As[nb][1][kh + j][ar] = v1[j]; As[nb][0][kh + j][ar] = v0[j]; }
        }
        if (s + 2 < NSTG) {
            int s2 = s + 2;
            aR1 = *(const uint4*)(a1p + s2 * 8);
            aR0 = *(const uint4*)(a0p + s2 * 8);
            cp16(bDst + (uint32_t)(s2 % 3) * 4096u, bp + (size_t)s2 * 8 * HID);
        }
        CP_COMMIT();
    }

    float4 bv = *(const float4*)(e_b1 + e * HID + nt + tx * 4);
    float sw0 = g_sw[e * HID + nt + tx * 4 + 0];
    float sw1 = g_sw[e * HID + nt + tx * 4 + 1];
    float sw2 = g_sw[e * HID + nt + tx * 4 + 2];
    float sw3 = g_sw[e * HID + nt + tx * 4 + 3];

    #pragma unroll
    for (int i = 0; i < 8; i++) {
        int r = ty * 8 + i;
        if (r >= Mblk) continue;
        float sa = sa_s[r];
        float c0 = sa * sw0 * (16384.f * (float)P11[i][0] + 128.f * (float)Pm[i][0]) + bv.x;
        float c1 = sa * sw1 * (16384.f * (float)P11[i][1] + 128.f * (float)Pm[i][1]) + bv.y;
        float c2 = sa * sw2 * (16384.f * (float)P11[i][2] + 128.f * (float)Pm[i][2]) + bv.z;
        float c3 = sa * sw3 * (16384.f * (float)P11[i][3] + 128.f * (float)Pm[i][3]) + bv.w;
        float4 o = make_float4(gelu_f(c0), gelu_f(c1), gelu_f(c2), gelu_f(c3));
        *(float4*)(g_eh + (size_t)(m_base + mt + r) * HID + nt + tx * 4) = o;
    }
}

// ---------- FFMA fc2 (round-11 verbatim) ----------
__global__ __launch_bounds__(256) void ffma_fc2(const float* __restrict__ W,
                                                const float* __restrict__ bias)
{
    const int BN = DMODEL, NS = HID / TK;
    int e = blockIdx.z;
    int m_base = g_off[e];
    int M = g_off[e + 1] - m_base;
    int mt = blockIdx.y * TM;
    if (mt >= M) return;
    int Mblk = min(TM, M - mt);
    int nt = blockIdx.x * TN;

    const float* Wp = W + (size_t)e * ((size_t)HID * DMODEL);
    const float* bi = bias + e * BN;

    extern __shared__ char smem[];
    uint32_t sb = smem_u32(smem);
    u64*      Adup   = (u64*)smem;
    uint32_t* Bsm    = (uint32_t*)(smem + SM_B0);
    int*      rowtok = (int*)(smem + SM_ROW);

    int t = threadIdx.x;
    if (t < TM) {
        int mm = mt + t;
        rowtok[t] = m_base + ((mm < M) ? mm : 0);
    }
    __syncthreads();

    int ar = t >> 1, kh = (t & 1) * 8;
    const float* aRow = g_eh + (size_t)rowtok[ar] * HID + kh;
    int bkr = t >> 4, bch = (t & 15) * 4;
    const float* bRow = Wp + (size_t)bkr * BN + nt + bch;
    uint32_t bDstBase = sb + SM_B0 + (uint32_t)(bkr * TN + bch) * 4u;

    int tx = t & 15, ty = t >> 4;
    u64 acc[8][2];
    #pragma unroll
    for (int i = 0; i < 8; i++) { acc[i][0] = 0ull; acc[i][1] = 0ull; }

    float4 aR0, aR1;
    aR0 = *(const float4*)(aRow);
    aR1 = *(const float4*)(aRow + 4);
    cp16(bDstBase, bRow);
    CP_COMMIT();
    {
        float v[8] = {aR0.x, aR0.y, aR0.z, aR0.w, aR1.x, aR1.y, aR1.z, aR1.w};
        #pragma unroll
        for (int i = 0; i < 8; i++) { u64 d; PACKDUP(d, v[i]); Adup[(kh + i) * TM + ar] = d; }
    }
    aR0 = *(const float4*)(aRow + TK);
    aR1 = *(const float4*)(aRow + TK + 4);
    cp16(bDstBase + 4096u, bRow + (size_t)TK * BN);
    CP_COMMIT();

    #pragma unroll 1
    for (int s = 0; s < NS; s++) {
        CP_WAIT(1);
        __syncthreads();
        const u64* Ad = Adup + (size_t)(s & 1) * (TK * TM);
        const uint32_t* Bb = Bsm + (size_t)(s % 3) * (TK * TN);

        #pragma unroll
        for (int k = 0; k < TK; k++) {
            u64 af[8];
            #pragma unroll
            for (int i = 0; i < 4; i++)
                *(ulonglong2*)&af[2 * i] = *(const ulonglong2*)&Ad[k * TM + ty * 8 + 2 * i];
            ulonglong2 bf = *(const ulonglong2*)&Bb[k * TN + tx * 4];
            #pragma unroll
            for (int i = 0; i < 8; i++) {
                FMA2(acc[i][0], af[i], bf.x);
                FMA2(acc[i][1], af[i], bf.y);
            }
        }

        if (s + 1 < NS) {
            u64* Aw = Adup + (size_t)((s + 1) & 1) * (TK * TM);
            float v[8] = {aR0.x, aR0.y, aR0.z, aR0.w, aR1.x, aR1.y, aR1.z, aR1.w};
            #pragma unroll
            for (int i = 0; i < 8; i++) { u64 d; PACKDUP(d, v[i]); Aw[(kh + i) * TM + ar] = d; }
        }
        if (s + 2 < NS) {
            int s2 = s + 2;
            aR0 = *(const float4*)(aRow + s2 * TK);
            aR1 = *(const float4*)(aRow + s2 * TK + 4);
            cp16(bDstBase + (uint32_t)(s2 % 3) * 4096u, bRow + (size_t)s2 * TK * BN);
        }
        CP_COMMIT();
    }

    float4 bv = *(const float4*)(bi + nt + tx * 4);
    #pragma unroll
    for (int i = 0; i < 8; i++) {
        int rloc = ty * 8 + i;
        if (rloc >= Mblk) continue;
        float c0, c1, c2, c3;
        UNPACK2(c0, c1, acc[i][0]);
        UNPACK2(c2, c3, acc[i][1]);
        c0 += bv.x; c1 += bv.y; c2 += bv.z; c3 += bv.w;
        int rr = m_base + mt + rloc;
        int token = g_rows_token[rr];
        int slot  = g_rows_slot[rr];
        float gw  = g_rows_w[rr];
        float4 o = make_float4(c0 * gw, c1 * gw, c2 * gw, c3 * gw);
        *(float4*)(g_outs + ((size_t)token * 2 + slot) * DMODEL + nt + tx * 4) = o;
    }
}

// ---------- router head ----------
__global__ __launch_bounds__(256) void router_head(
    const float* __restrict__ r_w2, const float* __restrict__ r_b2,
    const float* __restrict__ log_temp)
{
    __shared__ float w2s[RHID * NEXP];
    __shared__ float b2s[NEXP];
    int t = threadIdx.x;
    for (int i = t; i < RHID * NEXP; i += 256) w2s[i] = r_w2[i];
    if (t < NEXP) b2s[t] = r_b2[t];
    __syncthreads();

    int n = blockIdx.x * 256 + t;
    const float* rhp = g_rh + (size_t)n * RHID;
    float acc[NEXP];
    #pragma unroll
    for (int e = 0; e < NEXP; e++) acc[e] = b2s[e];
    for (int k = 0; k < RHID; k++) {
        float rv = rhp[k];
        #pragma unroll
        for (int e = 0; e < NEXP; e++) acc[e] = fmaf(rv, w2s[k * NEXP + e], acc[e]);
    }
    float temp = expf(*log_temp);
    temp = fminf(fmaxf(temp, 1e-3f), 100.f);
    float inv_t = 1.f / temp;
    #pragma unroll
    for (int e = 0; e < NEXP; e++) acc[e] *= inv_t;

    int i0 = 0;
    #pragma unroll
    for (int e = 1; e < NEXP; e++) if (acc[e] > acc[i0]) i0 = e;
    int i1 = (i0 == 0) ? 1 : 0;
    #pragma unroll
    for (int e = 0; e < NEXP; e++)
        if (e != i0 && acc[e] > acc[i1]) i1 = e;

    float e1 = expf(acc[i1] - acc[i0]);
    float inv_s = 1.f / (1.f + e1);
    g_topi[n * 2 + 0] = i0; g_topw[n * 2 + 0] = inv_s;
    g_topi[n * 2 + 1] = i1; g_topw[n * 2 + 1] = e1 * inv_s;
    atomicAdd(&g_cnt[i0], 1);
    atomicAdd(&g_cnt[i1], 1);
}

// ---------- bookkeeping ----------
__global__ __launch_bounds__(256) void zero_all() {
    int i = blockIdx.x * 256 + threadIdx.x;
    if (i < NEXP * HID) g_swmax[i] = 0u;
    if (i < NEXP) { g_cnt[i] = 0; g_cursor[i] = 0; }
}
__global__ void calc_offsets() {
    if (threadIdx.x == 0) {
        int s = 0;
        for (int e = 0; e < NEXP; e++) { g_off[e] = s; s += g_cnt[e]; }
        g_off[NEXP] = s;
    }
}
__global__ __launch_bounds__(256) void scatter_rows() {
    int n = blockIdx.x * 256 + threadIdx.x;
    if (n >= N_TOK) return;
    #pragma unroll
    for (int k = 0; k < 2; k++) {
        int e = g_topi[n * 2 + k];
        int pos = atomicAdd(&g_cursor[e], 1);
        int r = g_off[e] + pos;
        g_rows_token[r] = n;
        g_rows_slot[r] = k;
        g_rows_w[r] = g_topw[n * 2 + k];
    }
}

// ---------- combine + final LN ----------
__global__ __launch_bounds__(256) void combine_ln(
    const float* __restrict__ oln_g, const float* __restrict__ oln_b,
    float* __restrict__ out)
{
    int n = blockIdx.x, t = threadIdx.x, t1 = t + 256;
    __shared__ float red[16];
    size_t b0 = (size_t)(n * 2) * DMODEL, b1 = b0 + DMODEL, bz = (size_t)n * DMODEL;
    float v0 = g_outs[b0 + t]  + g_outs[b1 + t]  + g_zres[bz + t];
    float v1 = g_outs[b0 + t1] + g_outs[b1 + t1] + g_zres[bz + t1];
    float v2[2] = {v0 + v1, v0 * v0 + v1 * v1};
    blockReduceV<2>(v2, red);
    float m = v2[0] * (1.f / DMODEL);
    float rs = rsqrtf(v2[1] * (1.f / DMODEL) - m * m + LN_EPS);
    out[bz + t]  = (v0 - m) * rs * oln_g[t]  + oln_b[t];
    out[bz + t1] = (v1 - m) * rs * oln_g[t1] + oln_b[t1];
}

// ---------- launch ----------
extern "C" void kernel_launch(void* const* d_in, const int* in_sizes, int n_in,
                              void* d_out, int out_size)
{
    const float* z1    = (const float*)d_in[0];
    const float* z2    = (const float*)d_in[1];
    const float* z3    = (const float*)d_in[2];
    const float* mask  = (const float*)d_in[3];
    const float* ln_g  = (const float*)d_in[4];
    const float* ln_b  = (const float*)d_in[5];
    const float* lnp_g = (const float*)d_in[6];
    const float* lnp_b = (const float*)d_in[7];
    const float* oln_g = (const float*)d_in[8];
    const float* oln_b = (const float*)d_in[9];
    const float* r_w1  = (const float*)d_in[10];
    const float* r_b1  = (const float*)d_in[11];
    const float* r_w2  = (const float*)d_in[12];
    const float* r_b2  = (const float*)d_in[13];
    const float* log_temp = (const float*)d_in[14];
    const float* e_w1  = (const float*)d_in[15];
    const float* e_b1  = (const float*)d_in[16];
    const float* e_w2  = (const float*)d_in[17];
    const float* e_b2  = (const float*)d_in[18];
    float* out = (float*)d_out;

    zero_all<<<(NEXP * HID + 255) / 256, 256>>>();
    // build_x (8192 blocks) + wcolmax (928 blocks) co-scheduled
    build_x_colmax<<<N_TOK + 928, 256>>>(z1, z2, z3, mask, ln_g, ln_b,
                                         lnp_g, lnp_b, e_w1);
    // router fc1 (256 blocks) + quant_w (37120 blocks) co-scheduled
    router_plus_quantw<<<256 + 4 * KP4 * NEXP, 256, SMEM_TOTAL>>>(r_w1, r_b1, e_w1);

    router_head<<<N_TOK / 256, 256>>>(r_w2, r_b2, log_temp);
    calc_offsets<<<1, 32>>>();
    scatter_rows<<<N_TOK / 256, 256>>>();

    dp4a_fc1<<<dim3(HID / 64, NROWS / 128, NEXP), 256>>>(e_b1);
    ffma_fc2<<<dim3(DMODEL / TN, NROWS / TM, NEXP), 256, SMEM_TOTAL>>>(e_w2, e_b2);

    combine_ln<<<N_TOK, 256>>>(oln_g, oln_b, out);
}

// round 15
// speedup vs baseline: 1.0607x; 1.0607x over previous
#include <cuda_runtime.h>
#include <math.h>
#include <stdint.h>

#define N_TOK   8192
#define DMODEL  512
#define NEXP    8
#define HID     1024
#define RHID    256
#define INDIM   4611
#define XLD     4624
#define KP4     1160
#define NROWS   (N_TOK * 2)
#define LN_EPS  1e-5f
#define QMAXF   16256.0f

#define TM 128
#define TN 64
#define TK 16
#define SM_B0   32768u
#define SM_ROW  (32768u + 3u * 4096u)
#define SMEM_TOTAL (45056 + 512)

typedef unsigned long long u64;

__device__ __align__(16) float g_x[(size_t)N_TOK * XLD];
__device__ __align__(16) float g_zres[(size_t)N_TOK * DMODEL];
__device__ __align__(16) float g_rh[(size_t)N_TOK * RHID];
__device__ float g_topw[N_TOK * 2];
__device__ int   g_topi[N_TOK * 2];
__device__ int   g_cnt[NEXP];
__device__ int   g_off[NEXP + 1];
__device__ int   g_cursor[NEXP];
__device__ int   g_rows_token[NROWS];
__device__ int   g_rows_slot[NROWS];
__device__ float g_rows_w[NROWS];
__device__ __align__(16) float g_eh[(size_t)NROWS * HID];
__device__ __align__(16) float g_outs[(size_t)NROWS * DMODEL];
__device__ __align__(16) uint32_t g_xq1[(size_t)N_TOK * KP4];
__device__ __align__(16) uint32_t g_xq0[(size_t)N_TOK * KP4];
__device__ __align__(16) uint32_t g_wq1[(size_t)NEXP * KP4 * HID];
__device__ __align__(16) uint32_t g_wq0[(size_t)NEXP * KP4 * HID];
__device__ float    g_sa[N_TOK];
__device__ __align__(16) float    g_sw[NEXP * HID];
__device__ __align__(16) unsigned g_swmax[NEXP * HID];

__device__ __forceinline__ uint32_t smem_u32(const void* p) {
    uint32_t a;
    asm("{ .reg .u64 t; cvta.to.shared.u64 t, %1; cvt.u32.u64 %0, t; }" : "=r"(a) : "l"(p));
    return a;
}
#define FMA2(acc, a, b) asm("fma.rn.f32x2 %0, %1, %2, %0;" : "+l"(acc) : "l"(a), "l"(b))
#define PACKDUP(d, f) do { unsigned _u = __float_as_uint(f); \
    asm("mov.b64 %0, {%1, %2};" : "=l"(d) : "r"(_u), "r"(_u)); } while (0)
#define UNPACK2(lo, hi, v) do { unsigned _a, _b; \
    asm("mov.b64 {%0, %1}, %2;" : "=r"(_a), "=r"(_b) : "l"(v)); \
    lo = __uint_as_float(_a); hi = __uint_as_float(_b); } while (0)
__device__ __forceinline__ void cp16sz(uint32_t dst, const void* src, uint32_t sz) {
    asm volatile("cp.async.cg.shared.global [%0], [%1], 16, %2;" :: "r"(dst), "l"(src), "r"(sz) : "memory");
}
__device__ __forceinline__ void cp16(uint32_t dst, const void* src) {
    asm volatile("cp.async.cg.shared.global [%0], [%1], 16;" :: "r"(dst), "l"(src) : "memory");
}
#define CP_COMMIT() asm volatile("cp.async.commit_group;" ::: "memory")
#define CP_WAIT(n)  asm volatile("cp.async.wait_group %0;" :: "n"(n) : "memory")

__device__ __forceinline__ float gelu_f(float v) {
    return 0.5f * v * (1.0f + erff(v * 0.70710678118654752440f));
}
__device__ __forceinline__ void qsplit(float v, float inv, int& h, int& l) {
    int q = __float2int_rn(v * inv);
    h = (q + 64) >> 7;
    l = q - (h << 7);
}

template<int NV>
__device__ __forceinline__ void blockReduceV(float* v, float* sbuf) {
    int lane = threadIdx.x & 31, w = threadIdx.x >> 5;
    #pragma unroll
    for (int n = 0; n < NV; n++)
        #pragma unroll
        for (int o = 16; o; o >>= 1)
            v[n] += __shfl_xor_sync(0xffffffffu, v[n], o);
    if (lane == 0)
        #pragma unroll
        for (int n = 0; n < NV; n++) sbuf[w * NV + n] = v[n];
    __syncthreads();
    if (w == 0) {
        float a[NV];
        #pragma unroll
        for (int n = 0; n < NV; n++) {
            a[n] = (lane < 8) ? sbuf[lane * NV + n] : 0.f;
            #pragma unroll
            for (int o = 4; o; o >>= 1)
                a[n] += __shfl_xor_sync(0xffffffffu, a[n], o);
        }
        if (lane == 0)
            #pragma unroll
            for (int n = 0; n < NV; n++) sbuf[n] = a[n];
    }
    __syncthreads();
    #pragma unroll
    for (int n = 0; n < NV; n++) v[n] = sbuf[n];
    __syncthreads();
}

// ---------- build fused input x + fp32 store + fused quantization ----------
__global__ __launch_bounds__(256) void build_x_kernel(
    const float* __restrict__ z1, const float* __restrict__ z2,
    const float* __restrict__ z3, const float* __restrict__ mask,
    const float* __restrict__ ln_g, const float* __restrict__ ln_b,
    const float* __restrict__ lnp_g, const float* __restrict__ lnp_b)
{
    int n = blockIdx.x, t = threadIdx.x;
    __shared__ float a1[DMODEL], a2[DMODEL], a3[DMODEL];
    __shared__ float red[8 * 12];
    size_t zb = (size_t)n * DMODEL;
    int c0 = 2 * t, c1 = 2 * t + 1;

    float2 x1 = *(const float2*)(z1 + zb + c0);
    float2 x2 = *(const float2*)(z2 + zb + c0);
    float2 x3 = *(const float2*)(z3 + zb + c0);
    float2 gg = *(const float2*)(ln_g + c0);
    float2 bb = *(const float2*)(ln_b + c0);

    float v6[6] = {x1.x + x1.y, x1.x * x1.x + x1.y * x1.y,
                   x2.x + x2.y, x2.x * x2.x + x2.y * x2.y,
                   x3.x + x3.y, x3.x * x3.x + x3.y * x3.y};
    blockReduceV<6>(v6, red);

    float m, rs;
    m = v6[0] * (1.f / DMODEL);
    rs = rsqrtf(v6[1] * (1.f / DMODEL) - m * m + LN_EPS);
    float n1a = (x1.x - m) * rs * gg.x + bb.x, n1b = (x1.y - m) * rs * gg.y + bb.y;
    m = v6[2] * (1.f / DMODEL);
    rs = rsqrtf(v6[3] * (1.f / DMODEL) - m * m + LN_EPS);
    float n2a = (x2.x - m) * rs * gg.x + bb.x, n2b = (x2.y - m) * rs * gg.y + bb.y;
    m = v6[4] * (1.f / DMODEL);
    rs = rsqrtf(v6[5] * (1.f / DMODEL) - m * m + LN_EPS);
    float n3a = (x3.x - m) * rs * gg.x + bb.x, n3b = (x3.y - m) * rs * gg.y + bb.y;

    a1[c0] = n1a; a1[c1] = n1b;
    a2[c0] = n2a; a2[c1] = n2b;
    a3[c0] = n3a; a3[c1] = n3b;

    size_t xb = (size_t)n * XLD;
    g_x[xb + c0] = n1a;              g_x[xb + c1] = n1b;
    g_x[xb + 512 + c0] = n2a;        g_x[xb + 512 + c1] = n2b;
    g_x[xb + 1024 + c0] = n3a;       g_x[xb + 1024 + c1] = n3b;
    __syncthreads();

    float2 pg = *(const float2*)(lnp_g + c0);
    float2 pb = *(const float2*)(lnp_b + c0);
    const float* pp[6] = {a1, a1, a2, a1, a1, a2};
    const float* qq[6] = {a2, a3, a3, a2, a3, a3};
    float uv[6][2];
    float v12[12];
    #pragma unroll
    for (int c = 0; c < 6; c++) {
        float u0, u1;
        if (c < 3) { u0 = pp[c][c0] - qq[c][c0]; u1 = pp[c][c1] - qq[c][c1]; }
        else       { u0 = pp[c][c0] * qq[c][c0]; u1 = pp[c][c1] * qq[c][c1]; }
        uv[c][0] = u0; uv[c][1] = u1;
        v12[2 * c] = u0 + u1;
        v12[2 * c + 1] = u0 * u0 + u1 * u1;
    }
    blockReduceV<12>(v12, red);

    float dv[6][2];
    #pragma unroll
    for (int c = 0; c < 6; c++) {
        float md = v12[2 * c] * (1.f / DMODEL);
        float rsd = rsqrtf(v12[2 * c + 1] * (1.f / DMODEL) - md * md + LN_EPS);
        float v0 = (uv[c][0] - md) * rsd * pg.x + pb.x;
        float v1 = (uv[c][1] - md) * rsd * pg.y + pb.y;
        dv[c][0] = v0; dv[c][1] = v1;
        g_x[xb + (size_t)(3 + c) * 512 + c0] = v0;
        g_x[xb + (size_t)(3 + c) * 512 + c1] = v1;
    }

    float m0 = mask[n * 3 + 0], m1m = mask[n * 3 + 1], m2m = mask[n * 3 + 2];
    if (t < 3) g_x[xb + 4608 + t] = mask[n * 3 + t];
    if (t < 13) g_x[xb + 4611 + t] = 0.f;

    float den = fmaxf(m0 + m1m + m2m, 1.f);
    g_zres[zb + c0] = (m0 * n1a + m1m * n2a + m2m * n3a) / den;
    g_zres[zb + c1] = (m0 * n1b + m1m * n2b + m2m * n3b) / den;

    float sv[9][2] = {{n1a, n1b}, {n2a, n2b}, {n3a, n3b},
        {dv[0][0], dv[0][1]}, {dv[1][0], dv[1][1]}, {dv[2][0], dv[2][1]},
        {dv[3][0], dv[3][1]}, {dv[4][0], dv[4][1]}, {dv[5][0], dv[5][1]}};
    float mx = fmaxf(fmaxf(fabsf(m0), fabsf(m1m)), fabsf(m2m));
    #pragma unroll
    for (int c = 0; c < 9; c++)
        mx = fmaxf(mx, fmaxf(fabsf(sv[c][0]), fabsf(sv[c][1])));
    #pragma unroll
    for (int o = 16; o; o >>= 1) mx = fmaxf(mx, __shfl_xor_sync(0xffffffffu, mx, o));
    if ((t & 31) == 0) red[t >> 5] = mx;
    __syncthreads();
    if (t == 0) {
        float v = red[0];
        #pragma unroll
        for (int i = 1; i < 8; i++) v = fmaxf(v, red[i]);
        red[0] = fmaxf(v, 1e-20f);
        g_sa[n] = red[0] * (1.f / QMAXF);
    }
    __syncthreads();
    float inv = QMAXF / red[0];

    #pragma unroll
    for (int c = 0; c < 9; c++) {
        int h0, l0, h1, l1;
        qsplit(sv[c][0], inv, h0, l0);
        qsplit(sv[c][1], inv, h1, l1);
        uint32_t ph = (uint32_t)(h0 & 0xFF) | ((uint32_t)(h1 & 0xFF) << 8);
        uint32_t pl = (uint32_t)(l0 & 0xFF) | ((uint32_t)(l1 & 0xFF) << 8);
        uint32_t oh = __shfl_down_sync(0xffffffffu, ph, 1);
        uint32_t ol = __shfl_down_sync(0xffffffffu, pl, 1);
        if (!(t & 1)) {
            size_t gi = (size_t)n * KP4 + c * 128 + (t >> 1);
            g_xq1[gi] = ph | (oh << 16);
            g_xq0[gi] = pl | (ol << 16);
        }
    }
    if (t == 0) {
        int h0, l0, h1, l1, h2, l2;
        qsplit(m0, inv, h0, l0); qsplit(m1m, inv, h1, l1); qsplit(m2m, inv, h2, l2);
        size_t gi = (size_t)n * KP4 + 1152;
        g_xq1[gi] = (uint32_t)(h0 & 0xFF) | ((uint32_t)(h1 & 0xFF) << 8) | ((uint32_t)(h2 & 0xFF) << 16);
        g_xq0[gi] = (uint32_t)(l0 & 0xFF) | ((uint32_t)(l1 & 0xFF) << 8) | ((uint32_t)(l2 & 0xFF) << 16);
    }
    if (t >= 1 && t < 8) {
        size_t gi = (size_t)n * KP4 + 1152 + t;
        g_xq1[gi] = 0; g_xq0[gi] = 0;
    }
}

// ---------- expert weight scale + quantize (float4-vectorized) ----------
__global__ __launch_bounds__(256) void wcolmax(const float* __restrict__ e_w1) {
    // grid (1, NEXP, 29); thread t handles columns 4t..4t+3
    int t = threadIdx.x;
    int e = blockIdx.y, ks = blockIdx.z;
    int k0 = ks * 159, k1 = min(INDIM, k0 + 159);
    const float* W = e_w1 + (size_t)e * INDIM * HID + 4 * t;
    float m0 = 0.f, m1 = 0.f, m2 = 0.f, m3 = 0.f;
    #pragma unroll 4
    for (int k = k0; k < k1; k++) {
        float4 v = *(const float4*)(W + (size_t)k * HID);
        m0 = fmaxf(m0, fabsf(v.x)); m1 = fmaxf(m1, fabsf(v.y));
        m2 = fmaxf(m2, fabsf(v.z)); m3 = fmaxf(m3, fabsf(v.w));
    }
    int b = e * HID + 4 * t;
    atomicMax(&g_swmax[b + 0], __float_as_uint(m0));
    atomicMax(&g_swmax[b + 1], __float_as_uint(m1));
    atomicMax(&g_swmax[b + 2], __float_as_uint(m2));
    atomicMax(&g_swmax[b + 3], __float_as_uint(m3));
}
__global__ __launch_bounds__(256) void quant_w(const float* __restrict__ e_w1) {
    // grid (KP4, NEXP); thread t handles columns 4t..4t+3 for one k4 group
    int t = threadIdx.x;
    int k4 = blockIdx.x, e = blockIdx.y;
    int nb = e * HID + 4 * t;
    uint4 mxu = *(const uint4*)&g_swmax[nb];
    float mx[4] = {fmaxf(__uint_as_float(mxu.x), 1e-20f),
                   fmaxf(__uint_as_float(mxu.y), 1e-20f),
                   fmaxf(__uint_as_float(mxu.z), 1e-20f),
                   fmaxf(__uint_as_float(mxu.w), 1e-20f)};
    float invq[4] = {QMAXF / mx[0], QMAXF / mx[1], QMAXF / mx[2], QMAXF / mx[3]};
    if (k4 == 0) {
        float4 sw = make_float4(mx[0] * (1.f / QMAXF), mx[1] * (1.f / QMAXF),
                                mx[2] * (1.f / QMAXF), mx[3] * (1.f / QMAXF));
        *(float4*)&g_sw[nb] = sw;
    }
    uint32_t hw[4] = {0, 0, 0, 0}, lw[4] = {0, 0, 0, 0};
    const float* W = e_w1 + (size_t)e * INDIM * HID + 4 * t;
    #pragma unroll
    for (int j = 0; j < 4; j++) {
        int k = 4 * k4 + j;
        float4 v = (k < INDIM) ? *(const float4*)(W + (size_t)k * HID)
                               : make_float4(0.f, 0.f, 0.f, 0.f);
        float vv[4] = {v.x, v.y, v.z, v.w};
        #pragma unroll
        for (int c = 0; c < 4; c++) {
            int h, l;
            qsplit(vv[c], invq[c], h, l);
            hw[c] |= (uint32_t)(h & 0xFF) << (8 * j);
            lw[c] |= (uint32_t)(l & 0xFF) << (8 * j);
        }
    }
    size_t idx = ((size_t)e * KP4 + k4) * HID + 4 * t;
    *(uint4*)&g_wq1[idx] = make_uint4(hw[0], hw[1], hw[2], hw[3]);
    *(uint4*)&g_wq0[idx] = make_uint4(lw[0], lw[1], lw[2], lw[3]);
}

// ---------- dp4a expert fc1 (round-13 verbatim) ----------
__global__ __launch_bounds__(256, 2) void dp4a_fc1(const float* __restrict__ e_b1)
{
    __shared__ uint32_t As[2][2][8][128];
    __shared__ uint32_t Bs[3][2][8][64];
    __shared__ int   rt_s[128];
    __shared__ float sa_s[128];

    int e = blockIdx.z;
    int m_base = g_off[e];
    int M = g_off[e + 1] - m_base;
    int mt = blockIdx.y * 128;
    if (mt >= M) return;
    int Mblk = min(128, M - mt);
    int nt = blockIdx.x * 64;
    int t = threadIdx.x;

    if (t < 128) {
        int mm = mt + t;
        int tok = g_rows_token[m_base + ((mm < M) ? mm : 0)];
        rt_s[t] = tok;
        sa_s[t] = g_sa[tok];
    }
    __syncthreads();

    int ar = t >> 1, kh = (t & 1) * 4;
    const uint32_t* a1p = g_xq1 + (size_t)rt_s[ar] * KP4 + kh;
    const uint32_t* a0p = g_xq0 + (size_t)rt_s[ar] * KP4 + kh;

    int bl = t >> 7, bi_ = t & 127;
    int bk4 = bi_ >> 4, bn4 = (bi_ & 15) * 4;
    const uint32_t* bp = (bl ? g_wq1 : g_wq0) + ((size_t)e * KP4 + bk4) * HID + nt + bn4;
    uint32_t bDst = smem_u32(&Bs[0][bl][bk4][bn4]);

    int tx = t & 15, ty = t >> 4;
    int P11[8][4], Pm[8][4];
    #pragma unroll
    for (int i = 0; i < 8; i++)
        #pragma unroll
        for (int j = 0; j < 4; j++) { P11[i][j] = 0; Pm[i][j] = 0; }

    uint4 aR1, aR0;
    aR1 = *(const uint4*)a1p;
    aR0 = *(const uint4*)a0p;
    cp16(bDst, bp);
    CP_COMMIT();
    {
        uint32_t v1[4] = {aR1.x, aR1.y, aR1.z, aR1.w};
        uint32_t v0[4] = {aR0.x, aR0.y, aR0.z, aR0.w};
        #pragma unroll
        for (int j = 0; j < 4; j++) { As[0][1][kh + j][ar] = v1[j]; As[0][0][kh + j][ar] = v0[j]; }
    }
    aR1 = *(const uint4*)(a1p + 8);
    aR0 = *(const uint4*)(a0p + 8);
    cp16(bDst + 4096u, bp + 8 * HID);
    CP_COMMIT();

    const int NSTG = KP4 / 8;
    #pragma unroll 1
    for (int s = 0; s < NSTG; s++) {
        CP_WAIT(1);
        __syncthreads();
        int ab = s & 1, bb = s % 3;

        #pragma unroll
        for (int k4 = 0; k4 < 8; k4++) {
            uint4 f1a = *(const uint4*)&As[ab][1][k4][ty * 8];
            uint4 f1b = *(const uint4*)&As[ab][1][k4][ty * 8 + 4];
            uint4 f0a = *(const uint4*)&As[ab][0][k4][ty * 8];
            uint4 f0b = *(const uint4*)&As[ab][0][k4][ty * 8 + 4];
            uint4 bw1 = *(const uint4*)&Bs[bb][1][k4][tx * 4];
            uint4 bw0 = *(const uint4*)&Bs[bb][0][k4][tx * 4];
            uint32_t a1v[8] = {f1a.x, f1a.y, f1a.z, f1a.w, f1b.x, f1b.y, f1b.z, f1b.w};
            uint32_t a0v[8] = {f0a.x, f0a.y, f0a.z, f0a.w, f0b.x, f0b.y, f0b.z, f0b.w};
            uint32_t b1v[4] = {bw1.x, bw1.y, bw1.z, bw1.w};
            uint32_t b0v[4] = {bw0.x, bw0.y, bw0.z, bw0.w};
            #pragma unroll
            for (int i = 0; i < 8; i++)
                #pragma unroll
                for (int j = 0; j < 4; j++) {
                    P11[i][j] = __dp4a((int)a1v[i], (int)b1v[j], P11[i][j]);
                    Pm[i][j]  = __dp4a((int)a1v[i], (int)b0v[j], Pm[i][j]);
                    Pm[i][j]  = __dp4a((int)a0v[i], (int)b1v[j], Pm[i][j]);
                }
        }

        if (s + 1 < NSTG) {
            int nb = (s + 1) & 1;
            uint32_t v1[4] = {aR1.x, aR1.y, aR1.z, aR1.w};
            uint32_t v0[4] = {aR0.x, aR0.y, aR0.z, aR0.w};
            #pragma unroll
            for (int j = 0; j < 4; j++) { As[nb][1][kh + j][ar] = v1[j]; As[nb][0][kh + j][ar] = v0[j]; }
        }
        if (s + 2 < NSTG) {
            int s2 = s + 2;
            aR1 = *(const uint4*)(a1p + s2 * 8);
            aR0 = *(const uint4*)(a0p + s2 * 8);
            cp16(bDst + (uint32_t)(s2 % 3) * 4096u, bp + (size_t)s2 * 8 * HID);
        }
        CP_COMMIT();
    }

    float4 bv = *(const float4*)(e_b1 + e * HID + nt + tx * 4);
    float sw0 = g_sw[e * HID + nt + tx * 4 + 0];
    float sw1 = g_sw[e * HID + nt + tx * 4 + 1];
    float sw2 = g_sw[e * HID + nt + tx * 4 + 2];
    float sw3 = g_sw[e * HID + nt + tx * 4 + 3];

    #pragma unroll
    for (int i = 0; i < 8; i++) {
        int r = ty * 8 + i;
        if (r >= Mblk) continue;
        float sa = sa_s[r];
        float c0 = sa * sw0 * (16384.f * (float)P11[i][0] + 128.f * (float)Pm[i][0]) + bv.x;
        float c1 = sa * sw1 * (16384.f * (float)P11[i][1] + 128.f * (float)Pm[i][1]) + bv.y;
        float c2 = sa * sw2 * (16384.f * (float)P11[i][2] + 128.f * (float)Pm[i][2]) + bv.z;
        float c3 = sa * sw3 * (16384.f * (float)P11[i][3] + 128.f * (float)Pm[i][3]) + bv.w;
        float4 o = make_float4(gelu_f(c0), gelu_f(c1), gelu_f(c2), gelu_f(c3));
        *(float4*)(g_eh + (size_t)(m_base + mt + r) * HID + nt + tx * 4) = o;
    }
}

// ---------- FFMA GEMM (round-13 verbatim: MODE 0 router fc1, MODE 2 fc2) ---
template<int MODE>
__global__ __launch_bounds__(256) void ffma_gemm(const float* __restrict__ W,
                                                 const float* __restrict__ bias)
{
    constexpr int BN    = (MODE == 0) ? RHID : DMODEL;
    constexpr int KTOT  = (MODE == 2) ? HID : XLD;
    constexpr int KREAL = (MODE == 2) ? HID : INDIM;
    constexpr int NS    = KTOT / TK;

    int e = (MODE == 0) ? 0 : blockIdx.z;
    int m_base = 0, M;
    if (MODE == 0) M = N_TOK;
    else { m_base = g_off[e]; M = g_off[e + 1] - m_base; }
    int mt = blockIdx.y * TM;
    if (mt >= M) return;
    int Mblk = min(TM, M - mt);
    int nt = blockIdx.x * TN;

    const float* Wp = W;
    if (MODE == 2) Wp += (size_t)e * ((size_t)HID * DMODEL);
    const float* bi = bias + ((MODE == 0) ? 0 : e * BN);

    extern __shared__ char smem[];
    uint32_t sb = smem_u32(smem);
    u64*      Adup   = (u64*)smem;
    uint32_t* Bsm    = (uint32_t*)(smem + SM_B0);
    int*      rowtok = (int*)(smem + SM_ROW);

    int t = threadIdx.x;
    if (t < TM) {
        int mm = mt + t;
        rowtok[t] = (MODE == 0) ? ((mm < M) ? mm : mt) : (m_base + ((mm < M) ? mm : 0));
    }
    __syncthreads();

    const float* Asrc = (MODE == 2) ? g_eh : g_x;
    const int LDA = (MODE == 2) ? HID : XLD;

    int ar = t >> 1, kh = (t & 1) * 8;
    const float* aRow = Asrc + (size_t)rowtok[ar] * LDA + kh;
    int bkr = t >> 4, bch = (t & 15) * 4;
    const float* bRow = Wp + (size_t)bkr * BN + nt + bch;
    uint32_t bDstBase = sb + SM_B0 + (uint32_t)(bkr * TN + bch) * 4u;

    int tx = t & 15, ty = t >> 4;
    u64 acc[8][2];
    #pragma unroll
    for (int i = 0; i < 8; i++) { acc[i][0] = 0ull; acc[i][1] = 0ull; }

    float4 aR0, aR1;
    aR0 = *(const float4*)(aRow);
    aR1 = *(const float4*)(aRow + 4);
    cp16sz(bDstBase, (bkr < KREAL) ? bRow : Wp, (bkr < KREAL) ? 16u : 0u);
    CP_COMMIT();
    {
        float v[8] = {aR0.x, aR0.y, aR0.z, aR0.w, aR1.x, aR1.y, aR1.z, aR1.w};
        #pragma unroll
        for (int i = 0; i < 8; i++) { u64 d; PACKDUP(d, v[i]); Adup[(kh + i) * TM + ar] = d; }
    }
    aR0 = *(const float4*)(aRow + TK);
    aR1 = *(const float4*)(aRow + TK + 4);
    {
        int kb = TK + bkr;
        cp16sz(bDstBase + 4096u, (kb < KREAL) ? (bRow + (size_t)TK * BN) : Wp, (kb < KREAL) ? 16u : 0u);
    }
    CP_COMMIT();

    #pragma unroll 1
    for (int s = 0; s < NS; s++) {
        CP_WAIT(1);
        __syncthreads();
        const u64* Ad = Adup + (size_t)(s & 1) * (TK * TM);
        const uint32_t* Bb = Bsm + (size_t)(s % 3) * (TK * TN);

        #pragma unroll
        for (int k = 0; k < TK; k++) {
            u64 af[8];
            #pragma unroll
            for (int i = 0; i < 4; i++)
                *(ulonglong2*)&af[2 * i] = *(const ulonglong2*)&Ad[k * TM + ty * 8 + 2 * i];
            ulonglong2 bf = *(const ulonglong2*)&Bb[k * TN + tx * 4];
            #pragma unroll
            for (int i = 0; i < 8; i++) {
                FMA2(acc[i][0], af[i], bf.x);
                FMA2(acc[i][1], af[i], bf.y);
            }
        }

        if (s + 1 < NS) {
            u64* Aw = Adup + (size_t)((s + 1) & 1) * (TK * TM);
            float v[8] = {aR0.x, aR0.y, aR0.z, aR0.w, aR1.x, aR1.y, aR1.z, aR1.w};
            #pragma unroll
            for (int i = 0; i < 8; i++) { u64 d; PACKDUP(d, v[i]); Aw[(kh + i) * TM + ar] = d; }
        }
        if (s + 2 < NS) {
            int s2 = s + 2;
            aR0 = *(const float4*)(aRow + s2 * TK);
            aR1 = *(const float4*)(aRow + s2 * TK + 4);
            int kb = s2 * TK + bkr;
            cp16sz(bDstBase + (uint32_t)(s2 % 3) * 4096u,
                   (kb < KREAL) ? (bRow + (size_t)s2 * TK * BN) : Wp, (kb < KREAL) ? 16u : 0u);
        }
        CP_COMMIT();
    }

    float4 bv = *(const float4*)(bi + nt + tx * 4);
    #pragma unroll
    for (int i = 0; i < 8; i++) {
        int rloc = ty * 8 + i;
        if (rloc >= Mblk) continue;
        float c0, c1, c2, c3;
        UNPACK2(c0, c1, acc[i][0]);
        UNPACK2(c2, c3, acc[i][1]);
        c0 += bv.x; c1 += bv.y; c2 += bv.z; c3 += bv.w;
        if (MODE == 0) {
            float4 o = make_float4(gelu_f(c0), gelu_f(c1), gelu_f(c2), gelu_f(c3));
            *(float4*)(g_rh + (size_t)(mt + rloc) * RHID + nt + tx * 4) = o;
        } else {
            int rr = m_base + mt + rloc;
            int token = g_rows_token[rr];
            int slot  = g_rows_slot[rr];
            float gw  = g_rows_w[rr];
            float4 o = make_float4(c0 * gw, c1 * gw, c2 * gw, c3 * gw);
            *(float4*)(g_outs + ((size_t)token * 2 + slot) * DMODEL + nt + tx * 4) = o;
        }
    }
}

// ---------- router head (round-13 verbatim) ----------
__global__ __launch_bounds__(256) void router_head(
    const float* __restrict__ r_w2, const float* __restrict__ r_b2,
    const float* __restrict__ log_temp)
{
    __shared__ float w2s[RHID * NEXP];
    __shared__ float b2s[NEXP];
    int t = threadIdx.x;
    for (int i = t; i < RHID * NEXP; i += 256) w2s[i] = r_w2[i];
    if (t < NEXP) b2s[t] = r_b2[t];
    __syncthreads();

    int n = blockIdx.x * 256 + t;
    const float* rhp = g_rh + (size_t)n * RHID;
    float acc[NEXP];
    #pragma unroll
    for (int e = 0; e < NEXP; e++) acc[e] = b2s[e];
    for (int k = 0; k < RHID; k++) {
        float rv = rhp[k];
        #pragma unroll
        for (int e = 0; e < NEXP; e++) acc[e] = fmaf(rv, w2s[k * NEXP + e], acc[e]);
    }
    float temp = expf(*log_temp);
    temp = fminf(fmaxf(temp, 1e-3f), 100.f);
    float inv_t = 1.f / temp;
    #pragma unroll
    for (int e = 0; e < NEXP; e++) acc[e] *= inv_t;

    int i0 = 0;
    #pragma unroll
    for (int e = 1; e < NEXP; e++) if (acc[e] > acc[i0]) i0 = e;
    int i1 = (i0 == 0) ? 1 : 0;
    #pragma unroll
    for (int e = 0; e < NEXP; e++)
        if (e != i0 && acc[e] > acc[i1]) i1 = e;

    float e1 = expf(acc[i1] - acc[i0]);
    float inv_s = 1.f / (1.f + e1);
    g_topi[n * 2 + 0] = i0; g_topw[n * 2 + 0] = inv_s;
    g_topi[n * 2 + 1] = i1; g_topw[n * 2 + 1] = e1 * inv_s;
    atomicAdd(&g_cnt[i0], 1);
    atomicAdd(&g_cnt[i1], 1);
}

// ---------- bookkeeping ----------
__global__ __launch_bounds__(256) void zero_all() {
    int i = blockIdx.x * 256 + threadIdx.x;
    if (i < NEXP * HID) g_swmax[i] = 0u;
    if (i < NEXP) { g_cnt[i] = 0; g_cursor[i] = 0; }
}
__global__ void calc_offsets() {
    if (threadIdx.x == 0) {
        int s = 0;
        for (int e = 0; e < NEXP; e++) { g_off[e] = s; s += g_cnt[e]; }
        g_off[NEXP] = s;
    }
}
__global__ __launch_bounds__(256) void scatter_rows() {
    int n = blockIdx.x * 256 + threadIdx.x;
    if (n >= N_TOK) return;
    #pragma unroll
    for (int k = 0; k < 2; k++) {
        int e = g_topi[n * 2 + k];
        int pos = atomicAdd(&g_cursor[e], 1);
        int r = g_off[e] + pos;
        g_rows_token[r] = n;
        g_rows_slot[r] = k;
        g_rows_w[r] = g_topw[n * 2 + k];
    }
}

// ---------- combine + final LN ----------
__global__ __launch_bounds__(256) void combine_ln(
    const float* __restrict__ oln_g, const float* __restrict__ oln_b,
    float* __restrict__ out)
{
    int n = blockIdx.x, t = threadIdx.x, t1 = t + 256;
    __shared__ float red[16];
    size_t b0 = (size_t)(n * 2) * DMODEL, b1 = b0 + DMODEL, bz = (size_t)n * DMODEL;
    float v0 = g_outs[b0 + t]  + g_outs[b1 + t]  + g_zres[bz + t];
    float v1 = g_outs[b0 + t1] + g_outs[b1 + t1] + g_zres[bz + t1];
    float v2[2] = {v0 + v1, v0 * v0 + v1 * v1};
    blockReduceV<2>(v2, red);
    float m = v2[0] * (1.f / DMODEL);
    float rs = rsqrtf(v2[1] * (1.f / DMODEL) - m * m + LN_EPS);
    out[bz + t]  = (v0 - m) * rs * oln_g[t]  + oln_b[t];
    out[bz + t1] = (v1 - m) * rs * oln_g[t1] + oln_b[t1];
}

// ---------- launch ----------
extern "C" void kernel_launch(void* const* d_in, const int* in_sizes, int n_in,
                              void* d_out, int out_size)
{
    const float* z1    = (const float*)d_in[0];
    const float* z2    = (const float*)d_in[1];
    const float* z3    = (const float*)d_in[2];
    const float* mask  = (const float*)d_in[3];
    const float* ln_g  = (const float*)d_in[4];
    const float* ln_b  = (const float*)d_in[5];
    const float* lnp_g = (const float*)d_in[6];
    const float* lnp_b = (const float*)d_in[7];
    const float* oln_g = (const float*)d_in[8];
    const float* oln_b = (const float*)d_in[9];
    const float* r_w1  = (const float*)d_in[10];
    const float* r_b1  = (const float*)d_in[11];
    const float* r_w2  = (const float*)d_in[12];
    const float* r_b2  = (const float*)d_in[13];
    const float* log_temp = (const float*)d_in[14];
    const float* e_w1  = (const float*)d_in[15];
    const float* e_b1  = (const float*)d_in[16];
    const float* e_w2  = (const float*)d_in[17];
    const float* e_b2  = (const float*)d_in[18];
    float* out = (float*)d_out;

    zero_all<<<(NEXP * HID + 255) / 256, 256>>>();
    build_x_kernel<<<N_TOK, 256>>>(z1, z2, z3, mask, ln_g, ln_b, lnp_g, lnp_b);

    wcolmax<<<dim3(1, NEXP, 29), 256>>>(e_w1);
    quant_w<<<dim3(KP4, NEXP), 256>>>(e_w1);

    ffma_gemm<0><<<dim3(RHID / TN, N_TOK / TM, 1), 256, SMEM_TOTAL>>>(r_w1, r_b1);
    router_head<<<N_TOK / 256, 256>>>(r_w2, r_b2, log_temp);
    calc_offsets<<<1, 32>>>();
    scatter_rows<<<N_TOK / 256, 256>>>();

    dp4a_fc1<<<dim3(HID / 64, NROWS / 128, NEXP), 256>>>(e_b1);
    ffma_gemm<2><<<dim3(DMODEL / TN, NROWS / TM, NEXP), 256, SMEM_TOTAL>>>(e_w2, e_b2);

    combine_ln<<<N_TOK, 256>>>(oln_g, oln_b, out);
}

// round 16
// speedup vs baseline: 1.0763x; 1.0147x over previous
#include <cuda_runtime.h>
#include <math.h>
#include <stdint.h>

#define N_TOK   8192
#define DMODEL  512
#define NEXP    8
#define HID     1024
#define RHID    256
#define INDIM   4611
#define XLD     4624
#define KP4     1160
#define KP4H    256           // HID/4 k-groups for fc2
#define NROWS   (N_TOK * 2)
#define LN_EPS  1e-5f
#define QMAXF   16256.0f

#define TM 128
#define TN 64
#define TK 16
#define SM_B0   32768u
#define SM_ROW  (32768u + 3u * 4096u)
#define SMEM_TOTAL (45056 + 512)

typedef unsigned long long u64;

__device__ __align__(16) float g_x[(size_t)N_TOK * XLD];
__device__ __align__(16) float g_zres[(size_t)N_TOK * DMODEL];
__device__ __align__(16) float g_rh[(size_t)N_TOK * RHID];
__device__ float g_topw[N_TOK * 2];
__device__ int   g_topi[N_TOK * 2];
__device__ int   g_cnt[NEXP];
__device__ int   g_off[NEXP + 1];
__device__ int   g_cursor[NEXP];
__device__ int   g_rows_token[NROWS];
__device__ int   g_rows_slot[NROWS];
__device__ float g_rows_w[NROWS];
__device__ __align__(16) float g_eh[(size_t)NROWS * HID];
__device__ __align__(16) float g_outs[(size_t)NROWS * DMODEL];
__device__ __align__(16) uint32_t g_xq1[(size_t)N_TOK * KP4];
__device__ __align__(16) uint32_t g_xq0[(size_t)N_TOK * KP4];
__device__ __align__(16) uint32_t g_wq1[(size_t)NEXP * KP4 * HID];
__device__ __align__(16) uint32_t g_wq0[(size_t)NEXP * KP4 * HID];
__device__ __align__(16) uint32_t g_ehq1[(size_t)NROWS * KP4H];
__device__ __align__(16) uint32_t g_ehq0[(size_t)NROWS * KP4H];
__device__ __align__(16) uint32_t g_w2q1[(size_t)NEXP * KP4H * DMODEL];
__device__ __align__(16) uint32_t g_w2q0[(size_t)NEXP * KP4H * DMODEL];
__device__ float    g_sa[N_TOK];
__device__ float    g_seh[NROWS];
__device__ __align__(16) float    g_sw[NEXP * HID];
__device__ __align__(16) float    g_sw2[NEXP * DMODEL];
__device__ __align__(16) unsigned g_swmax[NEXP * HID];
__device__ __align__(16) unsigned g_sw2max[NEXP * DMODEL];

__device__ __forceinline__ uint32_t smem_u32(const void* p) {
    uint32_t a;
    asm("{ .reg .u64 t; cvta.to.shared.u64 t, %1; cvt.u32.u64 %0, t; }" : "=r"(a) : "l"(p));
    return a;
}
#define FMA2(acc, a, b) asm("fma.rn.f32x2 %0, %1, %2, %0;" : "+l"(acc) : "l"(a), "l"(b))
#define PACKDUP(d, f) do { unsigned _u = __float_as_uint(f); \
    asm("mov.b64 %0, {%1, %2};" : "=l"(d) : "r"(_u), "r"(_u)); } while (0)
#define UNPACK2(lo, hi, v) do { unsigned _a, _b; \
    asm("mov.b64 {%0, %1}, %2;" : "=r"(_a), "=r"(_b) : "l"(v)); \
    lo = __uint_as_float(_a); hi = __uint_as_float(_b); } while (0)
__device__ __forceinline__ void cp16sz(uint32_t dst, const void* src, uint32_t sz) {
    asm volatile("cp.async.cg.shared.global [%0], [%1], 16, %2;" :: "r"(dst), "l"(src), "r"(sz) : "memory");
}
__device__ __forceinline__ void cp16(uint32_t dst, const void* src) {
    asm volatile("cp.async.cg.shared.global [%0], [%1], 16;" :: "r"(dst), "l"(src) : "memory");
}
#define CP_COMMIT() asm volatile("cp.async.commit_group;" ::: "memory")
#define CP_WAIT(n)  asm volatile("cp.async.wait_group %0;" :: "n"(n) : "memory")

__device__ __forceinline__ float gelu_f(float v) {
    return 0.5f * v * (1.0f + erff(v * 0.70710678118654752440f));
}
__device__ __forceinline__ void qsplit(float v, float inv, int& h, int& l) {
    int q = __float2int_rn(v * inv);
    h = (q + 64) >> 7;
    l = q - (h << 7);
}

template<int NV>
__device__ __forceinline__ void blockReduceV(float* v, float* sbuf) {
    int lane = threadIdx.x & 31, w = threadIdx.x >> 5;
    #pragma unroll
    for (int n = 0; n < NV; n++)
        #pragma unroll
        for (int o = 16; o; o >>= 1)
            v[n] += __shfl_xor_sync(0xffffffffu, v[n], o);
    if (lane == 0)
        #pragma unroll
        for (int n = 0; n < NV; n++) sbuf[w * NV + n] = v[n];
    __syncthreads();
    if (w == 0) {
        float a[NV];
        #pragma unroll
        for (int n = 0; n < NV; n++) {
            a[n] = (lane < 8) ? sbuf[lane * NV + n] : 0.f;
            #pragma unroll
            for (int o = 4; o; o >>= 1)
                a[n] += __shfl_xor_sync(0xffffffffu, a[n], o);
        }
        if (lane == 0)
            #pragma unroll
            for (int n = 0; n < NV; n++) sbuf[n] = a[n];
    }
    __syncthreads();
    #pragma unroll
    for (int n = 0; n < NV; n++) v[n] = sbuf[n];
    __syncthreads();
}

// ---------- build fused input x + fp32 store + fused quantization ----------
__global__ __launch_bounds__(256) void build_x_kernel(
    const float* __restrict__ z1, const float* __restrict__ z2,
    const float* __restrict__ z3, const float* __restrict__ mask,
    const float* __restrict__ ln_g, const float* __restrict__ ln_b,
    const float* __restrict__ lnp_g, const float* __restrict__ lnp_b)
{
    int n = blockIdx.x, t = threadIdx.x;
    __shared__ float a1[DMODEL], a2[DMODEL], a3[DMODEL];
    __shared__ float red[8 * 12];
    size_t zb = (size_t)n * DMODEL;
    int c0 = 2 * t, c1 = 2 * t + 1;

    float2 x1 = *(const float2*)(z1 + zb + c0);
    float2 x2 = *(const float2*)(z2 + zb + c0);
    float2 x3 = *(const float2*)(z3 + zb + c0);
    float2 gg = *(const float2*)(ln_g + c0);
    float2 bb = *(const float2*)(ln_b + c0);

    float v6[6] = {x1.x + x1.y, x1.x * x1.x + x1.y * x1.y,
                   x2.x + x2.y, x2.x * x2.x + x2.y * x2.y,
                   x3.x + x3.y, x3.x * x3.x + x3.y * x3.y};
    blockReduceV<6>(v6, red);

    float m, rs;
    m = v6[0] * (1.f / DMODEL);
    rs = rsqrtf(v6[1] * (1.f / DMODEL) - m * m + LN_EPS);
    float n1a = (x1.x - m) * rs * gg.x + bb.x, n1b = (x1.y - m) * rs * gg.y + bb.y;
    m = v6[2] * (1.f / DMODEL);
    rs = rsqrtf(v6[3] * (1.f / DMODEL) - m * m + LN_EPS);
    float n2a = (x2.x - m) * rs * gg.x + bb.x, n2b = (x2.y - m) * rs * gg.y + bb.y;
    m = v6[4] * (1.f / DMODEL);
    rs = rsqrtf(v6[5] * (1.f / DMODEL) - m * m + LN_EPS);
    float n3a = (x3.x - m) * rs * gg.x + bb.x, n3b = (x3.y - m) * rs * gg.y + bb.y;

    a1[c0] = n1a; a1[c1] = n1b;
    a2[c0] = n2a; a2[c1] = n2b;
    a3[c0] = n3a; a3[c1] = n3b;

    size_t xb = (size_t)n * XLD;
    g_x[xb + c0] = n1a;              g_x[xb + c1] = n1b;
    g_x[xb + 512 + c0] = n2a;        g_x[xb + 512 + c1] = n2b;
    g_x[xb + 1024 + c0] = n3a;       g_x[xb + 1024 + c1] = n3b;
    __syncthreads();

    float2 pg = *(const float2*)(lnp_g + c0);
    float2 pb = *(const float2*)(lnp_b + c0);
    const float* pp[6] = {a1, a1, a2, a1, a1, a2};
    const float* qq[6] = {a2, a3, a3, a2, a3, a3};
    float uv[6][2];
    float v12[12];
    #pragma unroll
    for (int c = 0; c < 6; c++) {
        float u0, u1;
        if (c < 3) { u0 = pp[c][c0] - qq[c][c0]; u1 = pp[c][c1] - qq[c][c1]; }
        else       { u0 = pp[c][c0] * qq[c][c0]; u1 = pp[c][c1] * qq[c][c1]; }
        uv[c][0] = u0; uv[c][1] = u1;
        v12[2 * c] = u0 + u1;
        v12[2 * c + 1] = u0 * u0 + u1 * u1;
    }
    blockReduceV<12>(v12, red);

    float dv[6][2];
    #pragma unroll
    for (int c = 0; c < 6; c++) {
        float md = v12[2 * c] * (1.f / DMODEL);
        float rsd = rsqrtf(v12[2 * c + 1] * (1.f / DMODEL) - md * md + LN_EPS);
        float v0 = (uv[c][0] - md) * rsd * pg.x + pb.x;
        float v1 = (uv[c][1] - md) * rsd * pg.y + pb.y;
        dv[c][0] = v0; dv[c][1] = v1;
        g_x[xb + (size_t)(3 + c) * 512 + c0] = v0;
        g_x[xb + (size_t)(3 + c) * 512 + c1] = v1;
    }

    float m0 = mask[n * 3 + 0], m1m = mask[n * 3 + 1], m2m = mask[n * 3 + 2];
    if (t < 3) g_x[xb + 4608 + t] = mask[n * 3 + t];
    if (t < 13) g_x[xb + 4611 + t] = 0.f;

    float den = fmaxf(m0 + m1m + m2m, 1.f);
    g_zres[zb + c0] = (m0 * n1a + m1m * n2a + m2m * n3a) / den;
    g_zres[zb + c1] = (m0 * n1b + m1m * n2b + m2m * n3b) / den;

    float sv[9][2] = {{n1a, n1b}, {n2a, n2b}, {n3a, n3b},
        {dv[0][0], dv[0][1]}, {dv[1][0], dv[1][1]}, {dv[2][0], dv[2][1]},
        {dv[3][0], dv[3][1]}, {dv[4][0], dv[4][1]}, {dv[5][0], dv[5][1]}};
    float mx = fmaxf(fmaxf(fabsf(m0), fabsf(m1m)), fabsf(m2m));
    #pragma unroll
    for (int c = 0; c < 9; c++)
        mx = fmaxf(mx, fmaxf(fabsf(sv[c][0]), fabsf(sv[c][1])));
    #pragma unroll
    for (int o = 16; o; o >>= 1) mx = fmaxf(mx, __shfl_xor_sync(0xffffffffu, mx, o));
    if ((t & 31) == 0) red[t >> 5] = mx;
    __syncthreads();
    if (t == 0) {
        float v = red[0];
        #pragma unroll
        for (int i = 1; i < 8; i++) v = fmaxf(v, red[i]);
        red[0] = fmaxf(v, 1e-20f);
        g_sa[n] = red[0] * (1.f / QMAXF);
    }
    __syncthreads();
    float inv = QMAXF / red[0];

    #pragma unroll
    for (int c = 0; c < 9; c++) {
        int h0, l0, h1, l1;
        qsplit(sv[c][0], inv, h0, l0);
        qsplit(sv[c][1], inv, h1, l1);
        uint32_t ph = (uint32_t)(h0 & 0xFF) | ((uint32_t)(h1 & 0xFF) << 8);
        uint32_t pl = (uint32_t)(l0 & 0xFF) | ((uint32_t)(l1 & 0xFF) << 8);
        uint32_t oh = __shfl_down_sync(0xffffffffu, ph, 1);
        uint32_t ol = __shfl_down_sync(0xffffffffu, pl, 1);
        if (!(t & 1)) {
            size_t gi = (size_t)n * KP4 + c * 128 + (t >> 1);
            g_xq1[gi] = ph | (oh << 16);
            g_xq0[gi] = pl | (ol << 16);
        }
    }
    if (t == 0) {
        int h0, l0, h1, l1, h2, l2;
        qsplit(m0, inv, h0, l0); qsplit(m1m, inv, h1, l1); qsplit(m2m, inv, h2, l2);
        size_t gi = (size_t)n * KP4 + 1152;
        g_xq1[gi] = (uint32_t)(h0 & 0xFF) | ((uint32_t)(h1 & 0xFF) << 8) | ((uint32_t)(h2 & 0xFF) << 16);
        g_xq0[gi] = (uint32_t)(l0 & 0xFF) | ((uint32_t)(l1 & 0xFF) << 8) | ((uint32_t)(l2 & 0xFF) << 16);
    }
    if (t >= 1 && t < 8) {
        size_t gi = (size_t)n * KP4 + 1152 + t;
        g_xq1[gi] = 0; g_xq0[gi] = 0;
    }
}

// ---------- w1 scale + quantize (R15 vectorized) ----------
__global__ __launch_bounds__(256) void wcolmax(const float* __restrict__ e_w1) {
    int t = threadIdx.x;
    int e = blockIdx.y, ks = blockIdx.z;
    int k0 = ks * 159, k1 = min(INDIM, k0 + 159);
    const float* W = e_w1 + (size_t)e * INDIM * HID + 4 * t;
    float m0 = 0.f, m1 = 0.f, m2 = 0.f, m3 = 0.f;
    #pragma unroll 4
    for (int k = k0; k < k1; k++) {
        float4 v = *(const float4*)(W + (size_t)k * HID);
        m0 = fmaxf(m0, fabsf(v.x)); m1 = fmaxf(m1, fabsf(v.y));
        m2 = fmaxf(m2, fabsf(v.z)); m3 = fmaxf(m3, fabsf(v.w));
    }
    int b = e * HID + 4 * t;
    atomicMax(&g_swmax[b + 0], __float_as_uint(m0));
    atomicMax(&g_swmax[b + 1], __float_as_uint(m1));
    atomicMax(&g_swmax[b + 2], __float_as_uint(m2));
    atomicMax(&g_swmax[b + 3], __float_as_uint(m3));
}
__global__ __launch_bounds__(256) void quant_w(const float* __restrict__ e_w1) {
    int t = threadIdx.x;
    int k4 = blockIdx.x, e = blockIdx.y;
    int nb = e * HID + 4 * t;
    uint4 mxu = *(const uint4*)&g_swmax[nb];
    float mx[4] = {fmaxf(__uint_as_float(mxu.x), 1e-20f),
                   fmaxf(__uint_as_float(mxu.y), 1e-20f),
                   fmaxf(__uint_as_float(mxu.z), 1e-20f),
                   fmaxf(__uint_as_float(mxu.w), 1e-20f)};
    float invq[4] = {QMAXF / mx[0], QMAXF / mx[1], QMAXF / mx[2], QMAXF / mx[3]};
    if (k4 == 0) {
        float4 sw = make_float4(mx[0] * (1.f / QMAXF), mx[1] * (1.f / QMAXF),
                                mx[2] * (1.f / QMAXF), mx[3] * (1.f / QMAXF));
        *(float4*)&g_sw[nb] = sw;
    }
    uint32_t hw[4] = {0, 0, 0, 0}, lw[4] = {0, 0, 0, 0};
    const float* W = e_w1 + (size_t)e * INDIM * HID + 4 * t;
    #pragma unroll
    for (int j = 0; j < 4; j++) {
        int k = 4 * k4 + j;
        float4 v = (k < INDIM) ? *(const float4*)(W + (size_t)k * HID)
                               : make_float4(0.f, 0.f, 0.f, 0.f);
        float vv[4] = {v.x, v.y, v.z, v.w};
        #pragma unroll
        for (int c = 0; c < 4; c++) {
            int h, l;
            qsplit(vv[c], invq[c], h, l);
            hw[c] |= (uint32_t)(h & 0xFF) << (8 * j);
            lw[c] |= (uint32_t)(l & 0xFF) << (8 * j);
        }
    }
    size_t idx = ((size_t)e * KP4 + k4) * HID + 4 * t;
    *(uint4*)&g_wq1[idx] = make_uint4(hw[0], hw[1], hw[2], hw[3]);
    *(uint4*)&g_wq0[idx] = make_uint4(lw[0], lw[1], lw[2], lw[3]);
}

// ---------- w2 scale + quantize (vectorized; 128 threads, DMODEL=512) -------
__global__ __launch_bounds__(128) void wcolmax2(const float* __restrict__ e_w2) {
    int t = threadIdx.x;
    int e = blockIdx.y, ks = blockIdx.z;
    int k0 = ks * 64;
    const float* W = e_w2 + (size_t)e * HID * DMODEL + 4 * t;
    float m0 = 0.f, m1 = 0.f, m2 = 0.f, m3 = 0.f;
    #pragma unroll 4
    for (int k = k0; k < k0 + 64; k++) {
        float4 v = *(const float4*)(W + (size_t)k * DMODEL);
        m0 = fmaxf(m0, fabsf(v.x)); m1 = fmaxf(m1, fabsf(v.y));
        m2 = fmaxf(m2, fabsf(v.z)); m3 = fmaxf(m3, fabsf(v.w));
    }
    int b = e * DMODEL + 4 * t;
    atomicMax(&g_sw2max[b + 0], __float_as_uint(m0));
    atomicMax(&g_sw2max[b + 1], __float_as_uint(m1));
    atomicMax(&g_sw2max[b + 2], __float_as_uint(m2));
    atomicMax(&g_sw2max[b + 3], __float_as_uint(m3));
}
__global__ __launch_bounds__(128) void quant_w2(const float* __restrict__ e_w2) {
    int t = threadIdx.x;
    int k4 = blockIdx.x, e = blockIdx.y;
    int nb = e * DMODEL + 4 * t;
    uint4 mxu = *(const uint4*)&g_sw2max[nb];
    float mx[4] = {fmaxf(__uint_as_float(mxu.x), 1e-20f),
                   fmaxf(__uint_as_float(mxu.y), 1e-20f),
                   fmaxf(__uint_as_float(mxu.z), 1e-20f),
                   fmaxf(__uint_as_float(mxu.w), 1e-20f)};
    float invq[4] = {QMAXF / mx[0], QMAXF / mx[1], QMAXF / mx[2], QMAXF / mx[3]};
    if (k4 == 0) {
        float4 sw = make_float4(mx[0] * (1.f / QMAXF), mx[1] * (1.f / QMAXF),
                                mx[2] * (1.f / QMAXF), mx[3] * (1.f / QMAXF));
        *(float4*)&g_sw2[nb] = sw;
    }
    uint32_t hw[4] = {0, 0, 0, 0}, lw[4] = {0, 0, 0, 0};
    const float* W = e_w2 + (size_t)e * HID * DMODEL + 4 * t;
    #pragma unroll
    for (int j = 0; j < 4; j++) {
        float4 v = *(const float4*)(W + (size_t)(4 * k4 + j) * DMODEL);
        float vv[4] = {v.x, v.y, v.z, v.w};
        #pragma unroll
        for (int c = 0; c < 4; c++) {
            int h, l;
            qsplit(vv[c], invq[c], h, l);
            hw[c] |= (uint32_t)(h & 0xFF) << (8 * j);
            lw[c] |= (uint32_t)(l & 0xFF) << (8 * j);
        }
    }
    size_t idx = ((size_t)e * KP4H + k4) * DMODEL + 4 * t;
    *(uint4*)&g_w2q1[idx] = make_uint4(hw[0], hw[1], hw[2], hw[3]);
    *(uint4*)&g_w2q0[idx] = make_uint4(lw[0], lw[1], lw[2], lw[3]);
}

// ---------- eh rowmax + quantize (one block per gathered row) ---------------
__global__ __launch_bounds__(256) void quant_eh()
{
    int r = blockIdx.x, t = threadIdx.x;
    __shared__ float red[8];
    const float* ep = g_eh + (size_t)r * HID;
    float4 v = *(const float4*)(ep + 4 * t);
    float mx = fmaxf(fmaxf(fabsf(v.x), fabsf(v.y)), fmaxf(fabsf(v.z), fabsf(v.w)));
    #pragma unroll
    for (int o = 16; o; o >>= 1) mx = fmaxf(mx, __shfl_xor_sync(0xffffffffu, mx, o));
    if ((t & 31) == 0) red[t >> 5] = mx;
    __syncthreads();
    if (t == 0) {
        float m = red[0];
        #pragma unroll
        for (int i = 1; i < 8; i++) m = fmaxf(m, red[i]);
        red[0] = fmaxf(m, 1e-20f);
        g_seh[r] = red[0] * (1.f / QMAXF);
    }
    __syncthreads();
    float inv = QMAXF / red[0];
    float vv[4] = {v.x, v.y, v.z, v.w};
    uint32_t hw = 0, lw = 0;
    #pragma unroll
    for (int j = 0; j < 4; j++) {
        int h, l;
        qsplit(vv[j], inv, h, l);
        hw |= (uint32_t)(h & 0xFF) << (8 * j);
        lw |= (uint32_t)(l & 0xFF) << (8 * j);
    }
    g_ehq1[(size_t)r * KP4H + t] = hw;
    g_ehq0[(size_t)r * KP4H + t] = lw;
}

// ---------- dp4a GEMM core: MODE 1 = fc1, MODE 2 = fc2 ----------------------
template<int MODE>
__global__ __launch_bounds__(256, 2) void dp4a_fc(const float* __restrict__ bias)
{
    constexpr int BN  = (MODE == 1) ? HID : DMODEL;
    constexpr int KPX = (MODE == 1) ? KP4 : KP4H;
    __shared__ uint32_t As[2][2][8][128];
    __shared__ uint32_t Bs[3][2][8][64];
    __shared__ int   rt_s[128];
    __shared__ float sa_s[128];
    __shared__ int   slot_s[128];
    __shared__ float gw_s[128];

    int e = blockIdx.z;
    int m_base = g_off[e];
    int M = g_off[e + 1] - m_base;
    int mt = blockIdx.y * 128;
    if (mt >= M) return;
    int Mblk = min(128, M - mt);
    int nt = blockIdx.x * 64;
    int t = threadIdx.x;

    if (t < 128) {
        int mm = mt + t;
        int rr = m_base + ((mm < M) ? mm : 0);
        if (MODE == 1) {
            int tok = g_rows_token[rr];
            rt_s[t] = tok;
            sa_s[t] = g_sa[tok];
        } else {
            rt_s[t] = g_rows_token[rr];
            slot_s[t] = g_rows_slot[rr];
            gw_s[t] = g_rows_w[rr];
            sa_s[t] = g_seh[rr];
        }
    }
    __syncthreads();

    int ar = t >> 1, kh = (t & 1) * 4;
    const uint32_t* a1p;
    const uint32_t* a0p;
    if (MODE == 1) {
        a1p = g_xq1 + (size_t)rt_s[ar] * KPX + kh;
        a0p = g_xq0 + (size_t)rt_s[ar] * KPX + kh;
    } else {
        int rg = m_base + (((mt + ar) < M) ? (mt + ar) : 0);
        a1p = g_ehq1 + (size_t)rg * KPX + kh;
        a0p = g_ehq0 + (size_t)rg * KPX + kh;
    }

    int bl = t >> 7, bi_ = t & 127;
    int bk4 = bi_ >> 4, bn4 = (bi_ & 15) * 4;
    const uint32_t* bp;
    if (MODE == 1)
        bp = (bl ? g_wq1 : g_wq0) + ((size_t)e * KPX + bk4) * BN + nt + bn4;
    else
        bp = (bl ? g_w2q1 : g_w2q0) + ((size_t)e * KPX + bk4) * BN + nt + bn4;
    uint32_t bDst = smem_u32(&Bs[0][bl][bk4][bn4]);

    int tx = t & 15, ty = t >> 4;
    int P11[8][4], Pm[8][4];
    #pragma unroll
    for (int i = 0; i < 8; i++)
        #pragma unroll
        for (int j = 0; j < 4; j++) { P11[i][j] = 0; Pm[i][j] = 0; }

    uint4 aR1, aR0;
    aR1 = *(const uint4*)a1p;
    aR0 = *(const uint4*)a0p;
    cp16(bDst, bp);
    CP_COMMIT();
    {
        uint32_t v1[4] = {aR1.x, aR1.y, aR1.z, aR1.w};
        uint32_t v0[4] = {aR0.x, aR0.y, aR0.z, aR0.w};
        #pragma unroll
        for (int j = 0; j < 4; j++) { As[0][1][kh + j][ar] = v1[j]; As[0][0][kh + j][ar] = v0[j]; }
    }
    aR1 = *(const uint4*)(a1p + 8);
    aR0 = *(const uint4*)(a0p + 8);
    cp16(bDst + 4096u, bp + 8 * BN);
    CP_COMMIT();

    const int NSTG = KPX / 8;
    #pragma unroll 1
    for (int s = 0; s < NSTG; s++) {
        CP_WAIT(1);
        __syncthreads();
        int ab = s & 1, bb = s % 3;

        #pragma unroll
        for (int k4 = 0; k4 < 8; k4++) {
            uint4 f1a = *(const uint4*)&As[ab][1][k4][ty * 8];
            uint4 f1b = *(const uint4*)&As[ab][1][k4][ty * 8 + 4];
            uint4 f0a = *(const uint4*)&As[ab][0][k4][ty * 8];
            uint4 f0b = *(const uint4*)&As[ab][0][k4][ty * 8 + 4];
            uint4 bw1 = *(const uint4*)&Bs[bb][1][k4][tx * 4];
            uint4 bw0 = *(const uint4*)&Bs[bb][0][k4][tx * 4];
            uint32_t a1v[8] = {f1a.x, f1a.y, f1a.z, f1a.w, f1b.x, f1b.y, f1b.z, f1b.w};
            uint32_t a0v[8] = {f0a.x, f0a.y, f0a.z, f0a.w, f0b.x, f0b.y, f0b.z, f0b.w};
            uint32_t b1v[4] = {bw1.x, bw1.y, bw1.z, bw1.w};
            uint32_t b0v[4] = {bw0.x, bw0.y, bw0.z, bw0.w};
            #pragma unroll
            for (int i = 0; i < 8; i++)
                #pragma unroll
                for (int j = 0; j < 4; j++) {
                    P11[i][j] = __dp4a((int)a1v[i], (int)b1v[j], P11[i][j]);
                    Pm[i][j]  = __dp4a((int)a1v[i], (int)b0v[j], Pm[i][j]);
                    Pm[i][j]  = __dp4a((int)a0v[i], (int)b1v[j], Pm[i][j]);
                }
        }

        if (s + 1 < NSTG) {
            int nb = (s + 1) & 1;
            uint32_t v1[4] = {aR1.x, aR1.y, aR1.z, aR1.w};
            uint32_t v0[4] = {aR0.x, aR0.y, aR0.z, aR0.w};
            #pragma unroll
            for (int j = 0; j < 4; j++) { As[nb][1][kh + j][ar] = v1[j]; As[nb][0][kh + j][ar] = v0[j]; }
        }
        if (s + 2 < NSTG) {
            int s2 = s + 2;
            aR1 = *(const uint4*)(a1p + s2 * 8);
            aR0 = *(const uint4*)(a0p + s2 * 8);
            cp16(bDst + (uint32_t)(s2 % 3) * 4096u, bp + (size_t)s2 * 8 * BN);
        }
        CP_COMMIT();
    }

    float4 bv = *(const float4*)(bias + (size_t)e * BN + nt + tx * 4);
    const float* swp = ((MODE == 1) ? g_sw : g_sw2) + (size_t)e * BN + nt + tx * 4;
    float sw0 = swp[0], sw1 = swp[1], sw2 = swp[2], sw3 = swp[3];

    #pragma unroll
    for (int i = 0; i < 8; i++) {
        int r = ty * 8 + i;
        if (r >= Mblk) continue;
        float sa = sa_s[r];
        float c0 = sa * sw0 * (16384.f * (float)P11[i][0] + 128.f * (float)Pm[i][0]) + bv.x;
        float c1 = sa * sw1 * (16384.f * (float)P11[i][1] + 128.f * (float)Pm[i][1]) + bv.y;
        float c2 = sa * sw2 * (16384.f * (float)P11[i][2] + 128.f * (float)Pm[i][2]) + bv.z;
        float c3 = sa * sw3 * (16384.f * (float)P11[i][3] + 128.f * (float)Pm[i][3]) + bv.w;
        if (MODE == 1) {
            float4 o = make_float4(gelu_f(c0), gelu_f(c1), gelu_f(c2), gelu_f(c3));
            *(float4*)(g_eh + (size_t)(m_base + mt + r) * HID + nt + tx * 4) = o;
        } else {
            int token = rt_s[r];
            int slot  = slot_s[r];
            float gw  = gw_s[r];
            float4 o = make_float4(c0 * gw, c1 * gw, c2 * gw, c3 * gw);
            *(float4*)(g_outs + ((size_t)token * 2 + slot) * DMODEL + nt + tx * 4) = o;
        }
    }
}

// ---------- FFMA router fc1 (round-15 verbatim, MODE 0 only) ----------------
__global__ __launch_bounds__(256) void ffma_router(const float* __restrict__ W,
                                                   const float* __restrict__ bias)
{
    const int BN = RHID, NS = XLD / TK;
    int mt = blockIdx.y * TM;
    int nt = blockIdx.x * TN;

    extern __shared__ char smem[];
    uint32_t sb = smem_u32(smem);
    u64*      Adup = (u64*)smem;
    uint32_t* Bsm  = (uint32_t*)(smem + SM_B0);

    int t = threadIdx.x;
    int ar = t >> 1, kh = (t & 1) * 8;
    const float* aRow = g_x + (size_t)(mt + ar) * XLD + kh;
    int bkr = t >> 4, bch = (t & 15) * 4;
    const float* bRow = W + (size_t)bkr * BN + nt + bch;
    uint32_t bDstBase = sb + SM_B0 + (uint32_t)(bkr * TN + bch) * 4u;

    int tx = t & 15, ty = t >> 4;
    u64 acc[8][2];
    #pragma unroll
    for (int i = 0; i < 8; i++) { acc[i][0] = 0ull; acc[i][1] = 0ull; }

    float4 aR0, aR1;
    aR0 = *(const float4*)(aRow);
    aR1 = *(const float4*)(aRow + 4);
    cp16sz(bDstBase, (bkr < INDIM) ? bRow : W, (bkr < INDIM) ? 16u : 0u);
    CP_COMMIT();
    {
        float v[8] = {aR0.x, aR0.y, aR0.z, aR0.w, aR1.x, aR1.y, aR1.z, aR1.w};
        #pragma unroll
        for (int i = 0; i < 8; i++) { u64 d; PACKDUP(d, v[i]); Adup[(kh + i) * TM + ar] = d; }
    }
    aR0 = *(const float4*)(aRow + TK);
    aR1 = *(const float4*)(aRow + TK + 4);
    {
        int kb = TK + bkr;
        cp16sz(bDstBase + 4096u, (kb < INDIM) ? (bRow + (size_t)TK * BN) : W, (kb < INDIM) ? 16u : 0u);
    }
    CP_COMMIT();

    #pragma unroll 1
    for (int s = 0; s < NS; s++) {
        CP_WAIT(1);
        __syncthreads();
        const u64* Ad = Adup + (size_t)(s & 1) * (TK * TM);
        const uint32_t* Bb = Bsm + (size_t)(s % 3) * (TK * TN);

        #pragma unroll
        for (int k = 0; k < TK; k++) {
            u64 af[8];
            #pragma unroll
            for (int i = 0; i < 4; i++)
                *(ulonglong2*)&af[2 * i] = *(const ulonglong2*)&Ad[k * TM + ty * 8 + 2 * i];
            ulonglong2 bf = *(const ulonglong2*)&Bb[k * TN + tx * 4];
            #pragma unroll
            for (int i = 0; i < 8; i++) {
                FMA2(acc[i][0], af[i], bf.x);
                FMA2(acc[i][1], af[i], bf.y);
            }
        }

        if (s + 1 < NS) {
            u64* Aw = Adup + (size_t)((s + 1) & 1) * (TK * TM);
            float v[8] = {aR0.x, aR0.y, aR0.z, aR0.w, aR1.x, aR1.y, aR1.z, aR1.w};
            #pragma unroll
            for (int i = 0; i < 8; i++) { u64 d; PACKDUP(d, v[i]); Aw[(kh + i) * TM + ar] = d; }
        }
        if (s + 2 < NS) {
            int s2 = s + 2;
            aR0 = *(const float4*)(aRow + s2 * TK);
            aR1 = *(const float4*)(aRow + s2 * TK + 4);
            int kb = s2 * TK + bkr;
            cp16sz(bDstBase + (uint32_t)(s2 % 3) * 4096u,
                   (kb < INDIM) ? (bRow + (size_t)s2 * TK * BN) : W, (kb < INDIM) ? 16u : 0u);
        }
        CP_COMMIT();
    }

    float4 bv = *(const float4*)(bias + nt + tx * 4);
    #pragma unroll
    for (int i = 0; i < 8; i++) {
        int rloc = ty * 8 + i;
        float c0, c1, c2, c3;
        UNPACK2(c0, c1, acc[i][0]);
        UNPACK2(c2, c3, acc[i][1]);
        float4 o = make_float4(gelu_f(c0 + bv.x), gelu_f(c1 + bv.y),
                               gelu_f(c2 + bv.z), gelu_f(c3 + bv.w));
        *(float4*)(g_rh + (size_t)(mt + rloc) * RHID + nt + tx * 4) = o;
    }
}

// ---------- router head ----------
__global__ __launch_bounds__(256) void router_head(
    const float* __restrict__ r_w2, const float* __restrict__ r_b2,
    const float* __restrict__ log_temp)
{
    __shared__ float w2s[RHID * NEXP];
    __shared__ float b2s[NEXP];
    int t = threadIdx.x;
    for (int i = t; i < RHID * NEXP; i += 256) w2s[i] = r_w2[i];
    if (t < NEXP) b2s[t] = r_b2[t];
    __syncthreads();

    int n = blockIdx.x * 256 + t;
    const float* rhp = g_rh + (size_t)n * RHID;
    float acc[NEXP];
    #pragma unroll
    for (int e = 0; e < NEXP; e++) acc[e] = b2s[e];
    for (int k = 0; k < RHID; k++) {
        float rv = rhp[k];
        #pragma unroll
        for (int e = 0; e < NEXP; e++) acc[e] = fmaf(rv, w2s[k * NEXP + e], acc[e]);
    }
    float temp = expf(*log_temp);
    temp = fminf(fmaxf(temp, 1e-3f), 100.f);
    float inv_t = 1.f / temp;
    #pragma unroll
    for (int e = 0; e < NEXP; e++) acc[e] *= inv_t;

    int i0 = 0;
    #pragma unroll
    for (int e = 1; e < NEXP; e++) if (acc[e] > acc[i0]) i0 = e;
    int i1 = (i0 == 0) ? 1 : 0;
    #pragma unroll
    for (int e = 0; e < NEXP; e++)
        if (e != i0 && acc[e] > acc[i1]) i1 = e;

    float e1 = expf(acc[i1] - acc[i0]);
    float inv_s = 1.f / (1.f + e1);
    g_topi[n * 2 + 0] = i0; g_topw[n * 2 + 0] = inv_s;
    g_topi[n * 2 + 1] = i1; g_topw[n * 2 + 1] = e1 * inv_s;
    atomicAdd(&g_cnt[i0], 1);
    atomicAdd(&g_cnt[i1], 1);
}

// ---------- bookkeeping ----------
__global__ __launch_bounds__(256) void zero_all() {
    int i = blockIdx.x * 256 + threadIdx.x;
    if (i < NEXP * HID) g_swmax[i] = 0u;
    if (i < NEXP * DMODEL) g_sw2max[i] = 0u;
    if (i < NEXP) { g_cnt[i] = 0; g_cursor[i] = 0; }
}
__global__ void calc_offsets() {
    if (threadIdx.x == 0) {
        int s = 0;
        for (int e = 0; e < NEXP; e++) { g_off[e] = s; s += g_cnt[e]; }
        g_off[NEXP] = s;
    }
}
__global__ __launch_bounds__(256) void scatter_rows() {
    int n = blockIdx.x * 256 + threadIdx.x;
    if (n >= N_TOK) return;
    #pragma unroll
    for (int k = 0; k < 2; k++) {
        int e = g_topi[n * 2 + k];
        int pos = atomicAdd(&g_cursor[e], 1);
        int r = g_off[e] + pos;
        g_rows_token[r] = n;
        g_rows_slot[r] = k;
        g_rows_w[r] = g_topw[n * 2 + k];
    }
}

// ---------- combine + final LN ----------
__global__ __launch_bounds__(256) void combine_ln(
    const float* __restrict__ oln_g, const float* __restrict__ oln_b,
    float* __restrict__ out)
{
    int n = blockIdx.x, t = threadIdx.x, t1 = t + 256;
    __shared__ float red[16];
    size_t b0 = (size_t)(n * 2) * DMODEL, b1 = b0 + DMODEL, bz = (size_t)n * DMODEL;
    float v0 = g_outs[b0 + t]  + g_outs[b1 + t]  + g_zres[bz + t];
    float v1 = g_outs[b0 + t1] + g_outs[b1 + t1] + g_zres[bz + t1];
    float v2[2] = {v0 + v1, v0 * v0 + v1 * v1};
    blockReduceV<2>(v2, red);
    float m = v2[0] * (1.f / DMODEL);
    float rs = rsqrtf(v2[1] * (1.f / DMODEL) - m * m + LN_EPS);
    out[bz + t]  = (v0 - m) * rs * oln_g[t]  + oln_b[t];
    out[bz + t1] = (v1 - m) * rs * oln_g[t1] + oln_b[t1];
}

// ---------- launch ----------
extern "C" void kernel_launch(void* const* d_in, const int* in_sizes, int n_in,
                              void* d_out, int out_size)
{
    const float* z1    = (const float*)d_in[0];
    const float* z2    = (const float*)d_in[1];
    const float* z3    = (const float*)d_in[2];
    const float* mask  = (const float*)d_in[3];
    const float* ln_g  = (const float*)d_in[4];
    const float* ln_b  = (const float*)d_in[5];
    const float* lnp_g = (const float*)d_in[6];
    const float* lnp_b = (const float*)d_in[7];
    const float* oln_g = (const float*)d_in[8];
    const float* oln_b = (const float*)d_in[9];
    const float* r_w1  = (const float*)d_in[10];
    const float* r_b1  = (const float*)d_in[11];
    const float* r_w2  = (const float*)d_in[12];
    const float* r_b2  = (const float*)d_in[13];
    const float* log_temp = (const float*)d_in[14];
    const float* e_w1  = (const float*)d_in[15];
    const float* e_b1  = (const float*)d_in[16];
    const float* e_w2  = (const float*)d_in[17];
    const float* e_b2  = (const float*)d_in[18];
    float* out = (float*)d_out;

    zero_all<<<(NEXP * HID + 255) / 256, 256>>>();
    build_x_kernel<<<N_TOK, 256>>>(z1, z2, z3, mask, ln_g, ln_b, lnp_g, lnp_b);

    wcolmax<<<dim3(1, NEXP, 29), 256>>>(e_w1);
    quant_w<<<dim3(KP4, NEXP), 256>>>(e_w1);
    wcolmax2<<<dim3(1, NEXP, 16), 128>>>(e_w2);
    quant_w2<<<dim3(KP4H, NEXP), 128>>>(e_w2);

    ffma_router<<<dim3(RHID / TN, N_TOK / TM, 1), 256, SMEM_TOTAL>>>(r_w1, r_b1);
    router_head<<<N_TOK / 256, 256>>>(r_w2, r_b2, log_temp);
    calc_offsets<<<1, 32>>>();
    scatter_rows<<<N_TOK / 256, 256>>>();

    dp4a_fc<1><<<dim3(HID / 64, NROWS / 128, NEXP), 256>>>(e_b1);
    quant_eh<<<NROWS, 256>>>();
    dp4a_fc<2><<<dim3(DMODEL / 64, NROWS / 128, NEXP), 256>>>(e_b2);

    combine_ln<<<N_TOK, 256>>>(oln_g, oln_b, out);
}

// round 17
// speedup vs baseline: 1.0777x; 1.0013x over previous
#include <cuda_runtime.h>
#include <math.h>
#include <stdint.h>

#define N_TOK   8192
#define DMODEL  512
#define NEXP    8
#define HID     1024
#define RHID    256
#define INDIM   4611
#define XLD     4624
#define KP4     1160
#define KP4H    256
#define NROWS   (N_TOK * 2)
#define LN_EPS  1e-5f
#define QMAXF   16256.0f

#define TM 128
#define TN 64
#define TK 16
#define SM_B0   32768u
#define SMEM_TOTAL (45056 + 512)

typedef unsigned long long u64;

__device__ __align__(16) float g_x[(size_t)N_TOK * XLD];
__device__ __align__(16) float g_zres[(size_t)N_TOK * DMODEL];
__device__ __align__(16) float g_rh[(size_t)N_TOK * RHID];
__device__ float g_topw[N_TOK * 2];
__device__ int   g_topi[N_TOK * 2];
__device__ int   g_cnt[NEXP];
__device__ int   g_off[NEXP + 1];
__device__ int   g_cursor[NEXP];
__device__ int   g_rows_token[NROWS];
__device__ int   g_rows_slot[NROWS];
__device__ float g_rows_w[NROWS];
__device__ __align__(16) float g_eh[(size_t)NROWS * HID];
__device__ __align__(16) float g_outs[(size_t)NROWS * DMODEL];
__device__ __align__(16) uint32_t g_xq1[(size_t)N_TOK * KP4];
__device__ __align__(16) uint32_t g_xq0[(size_t)N_TOK * KP4];
__device__ __align__(16) uint32_t g_wq1[(size_t)NEXP * KP4 * HID];
__device__ __align__(16) uint32_t g_wq0[(size_t)NEXP * KP4 * HID];
__device__ __align__(16) uint32_t g_ehq1[(size_t)NROWS * KP4H];
__device__ __align__(16) uint32_t g_ehq0[(size_t)NROWS * KP4H];
__device__ __align__(16) uint32_t g_w2q1[(size_t)NEXP * KP4H * DMODEL];
__device__ __align__(16) uint32_t g_w2q0[(size_t)NEXP * KP4H * DMODEL];
__device__ float    g_sa[N_TOK];
__device__ float    g_seh[NROWS];
__device__ __align__(16) float    g_sw[NEXP * HID];
__device__ __align__(16) float    g_sw2[NEXP * DMODEL];
__device__ __align__(16) unsigned g_swmax[NEXP * HID];
__device__ __align__(16) unsigned g_sw2max[NEXP * DMODEL];

__device__ __forceinline__ uint32_t smem_u32(const void* p) {
    uint32_t a;
    asm("{ .reg .u64 t; cvta.to.shared.u64 t, %1; cvt.u32.u64 %0, t; }" : "=r"(a) : "l"(p));
    return a;
}
#define FMA2(acc, a, b) asm("fma.rn.f32x2 %0, %1, %2, %0;" : "+l"(acc) : "l"(a), "l"(b))
#define PACKDUP(d, f) do { unsigned _u = __float_as_uint(f); \
    asm("mov.b64 %0, {%1, %2};" : "=l"(d) : "r"(_u), "r"(_u)); } while (0)
#define UNPACK2(lo, hi, v) do { unsigned _a, _b; \
    asm("mov.b64 {%0, %1}, %2;" : "=r"(_a), "=r"(_b) : "l"(v)); \
    lo = __uint_as_float(_a); hi = __uint_as_float(_b); } while (0)
__device__ __forceinline__ void cp16sz(uint32_t dst, const void* src, uint32_t sz) {
    asm volatile("cp.async.cg.shared.global [%0], [%1], 16, %2;" :: "r"(dst), "l"(src), "r"(sz) : "memory");
}
__device__ __forceinline__ void cp16(uint32_t dst, const void* src) {
    asm volatile("cp.async.cg.shared.global [%0], [%1], 16;" :: "r"(dst), "l"(src) : "memory");
}
#define CP_COMMIT() asm volatile("cp.async.commit_group;" ::: "memory")
#define CP_WAIT(n)  asm volatile("cp.async.wait_group %0;" :: "n"(n) : "memory")

__device__ __forceinline__ float gelu_f(float v) {
    return 0.5f * v * (1.0f + erff(v * 0.70710678118654752440f));
}
__device__ __forceinline__ void qsplit(float v, float inv, int& h, int& l) {
    int q = __float2int_rn(v * inv);
    h = (q + 64) >> 7;
    l = q - (h << 7);
}

template<int NV>
__device__ __forceinline__ void blockReduceV(float* v, float* sbuf) {
    int lane = threadIdx.x & 31, w = threadIdx.x >> 5;
    #pragma unroll
    for (int n = 0; n < NV; n++)
        #pragma unroll
        for (int o = 16; o; o >>= 1)
            v[n] += __shfl_xor_sync(0xffffffffu, v[n], o);
    if (lane == 0)
        #pragma unroll
        for (int n = 0; n < NV; n++) sbuf[w * NV + n] = v[n];
    __syncthreads();
    if (w == 0) {
        float a[NV];
        #pragma unroll
        for (int n = 0; n < NV; n++) {
            a[n] = (lane < 8) ? sbuf[lane * NV + n] : 0.f;
            #pragma unroll
            for (int o = 4; o; o >>= 1)
                a[n] += __shfl_xor_sync(0xffffffffu, a[n], o);
        }
        if (lane == 0)
            #pragma unroll
            for (int n = 0; n < NV; n++) sbuf[n] = a[n];
    }
    __syncthreads();
    #pragma unroll
    for (int n = 0; n < NV; n++) v[n] = sbuf[n];
    __syncthreads();
}

// ---------- build fused input x + fp32 store + fused quantization ----------
__global__ __launch_bounds__(256) void build_x_kernel(
    const float* __restrict__ z1, const float* __restrict__ z2,
    const float* __restrict__ z3, const float* __restrict__ mask,
    const float* __restrict__ ln_g, const float* __restrict__ ln_b,
    const float* __restrict__ lnp_g, const float* __restrict__ lnp_b)
{
    int n = blockIdx.x, t = threadIdx.x;
    __shared__ float a1[DMODEL], a2[DMODEL], a3[DMODEL];
    __shared__ float red[8 * 12];
    size_t zb = (size_t)n * DMODEL;
    int c0 = 2 * t, c1 = 2 * t + 1;

    float2 x1 = *(const float2*)(z1 + zb + c0);
    float2 x2 = *(const float2*)(z2 + zb + c0);
    float2 x3 = *(const float2*)(z3 + zb + c0);
    float2 gg = *(const float2*)(ln_g + c0);
    float2 bb = *(const float2*)(ln_b + c0);

    float v6[6] = {x1.x + x1.y, x1.x * x1.x + x1.y * x1.y,
                   x2.x + x2.y, x2.x * x2.x + x2.y * x2.y,
                   x3.x + x3.y, x3.x * x3.x + x3.y * x3.y};
    blockReduceV<6>(v6, red);

    float m, rs;
    m = v6[0] * (1.f / DMODEL);
    rs = rsqrtf(v6[1] * (1.f / DMODEL) - m * m + LN_EPS);
    float n1a = (x1.x - m) * rs * gg.x + bb.x, n1b = (x1.y - m) * rs * gg.y + bb.y;
    m = v6[2] * (1.f / DMODEL);
    rs = rsqrtf(v6[3] * (1.f / DMODEL) - m * m + LN_EPS);
    float n2a = (x2.x - m) * rs * gg.x + bb.x, n2b = (x2.y - m) * rs * gg.y + bb.y;
    m = v6[4] * (1.f / DMODEL);
    rs = rsqrtf(v6[5] * (1.f / DMODEL) - m * m + LN_EPS);
    float n3a = (x3.x - m) * rs * gg.x + bb.x, n3b = (x3.y - m) * rs * gg.y + bb.y;

    a1[c0] = n1a; a1[c1] = n1b;
    a2[c0] = n2a; a2[c1] = n2b;
    a3[c0] = n3a; a3[c1] = n3b;

    size_t xb = (size_t)n * XLD;
    g_x[xb + c0] = n1a;              g_x[xb + c1] = n1b;
    g_x[xb + 512 + c0] = n2a;        g_x[xb + 512 + c1] = n2b;
    g_x[xb + 1024 + c0] = n3a;       g_x[xb + 1024 + c1] = n3b;
    __syncthreads();

    float2 pg = *(const float2*)(lnp_g + c0);
    float2 pb = *(const float2*)(lnp_b + c0);
    const float* pp[6] = {a1, a1, a2, a1, a1, a2};
    const float* qq[6] = {a2, a3, a3, a2, a3, a3};
    float uv[6][2];
    float v12[12];
    #pragma unroll
    for (int c = 0; c < 6; c++) {
        float u0, u1;
        if (c < 3) { u0 = pp[c][c0] - qq[c][c0]; u1 = pp[c][c1] - qq[c][c1]; }
        else       { u0 = pp[c][c0] * qq[c][c0]; u1 = pp[c][c1] * qq[c][c1]; }
        uv[c][0] = u0; uv[c][1] = u1;
        v12[2 * c] = u0 + u1;
        v12[2 * c + 1] = u0 * u0 + u1 * u1;
    }
    blockReduceV<12>(v12, red);

    float dv[6][2];
    #pragma unroll
    for (int c = 0; c < 6; c++) {
        float md = v12[2 * c] * (1.f / DMODEL);
        float rsd = rsqrtf(v12[2 * c + 1] * (1.f / DMODEL) - md * md + LN_EPS);
        float v0 = (uv[c][0] - md) * rsd * pg.x + pb.x;
        float v1 = (uv[c][1] - md) * rsd * pg.y + pb.y;
        dv[c][0] = v0; dv[c][1] = v1;
        g_x[xb + (size_t)(3 + c) * 512 + c0] = v0;
        g_x[xb + (size_t)(3 + c) * 512 + c1] = v1;
    }

    float m0 = mask[n * 3 + 0], m1m = mask[n * 3 + 1], m2m = mask[n * 3 + 2];
    if (t < 3) g_x[xb + 4608 + t] = mask[n * 3 + t];
    if (t < 13) g_x[xb + 4611 + t] = 0.f;

    float den = fmaxf(m0 + m1m + m2m, 1.f);
    g_zres[zb + c0] = (m0 * n1a + m1m * n2a + m2m * n3a) / den;
    g_zres[zb + c1] = (m0 * n1b + m1m * n2b + m2m * n3b) / den;

    float sv[9][2] = {{n1a, n1b}, {n2a, n2b}, {n3a, n3b},
        {dv[0][0], dv[0][1]}, {dv[1][0], dv[1][1]}, {dv[2][0], dv[2][1]},
        {dv[3][0], dv[3][1]}, {dv[4][0], dv[4][1]}, {dv[5][0], dv[5][1]}};
    float mx = fmaxf(fmaxf(fabsf(m0), fabsf(m1m)), fabsf(m2m));
    #pragma unroll
    for (int c = 0; c < 9; c++)
        mx = fmaxf(mx, fmaxf(fabsf(sv[c][0]), fabsf(sv[c][1])));
    #pragma unroll
    for (int o = 16; o; o >>= 1) mx = fmaxf(mx, __shfl_xor_sync(0xffffffffu, mx, o));
    if ((t & 31) == 0) red[t >> 5] = mx;
    __syncthreads();
    if (t == 0) {
        float v = red[0];
        #pragma unroll
        for (int i = 1; i < 8; i++) v = fmaxf(v, red[i]);
        red[0] = fmaxf(v, 1e-20f);
        g_sa[n] = red[0] * (1.f / QMAXF);
    }
    __syncthreads();
    float inv = QMAXF / red[0];

    #pragma unroll
    for (int c = 0; c < 9; c++) {
        int h0, l0, h1, l1;
        qsplit(sv[c][0], inv, h0, l0);
        qsplit(sv[c][1], inv, h1, l1);
        uint32_t ph = (uint32_t)(h0 & 0xFF) | ((uint32_t)(h1 & 0xFF) << 8);
        uint32_t pl = (uint32_t)(l0 & 0xFF) | ((uint32_t)(l1 & 0xFF) << 8);
        uint32_t oh = __shfl_down_sync(0xffffffffu, ph, 1);
        uint32_t ol = __shfl_down_sync(0xffffffffu, pl, 1);
        if (!(t & 1)) {
            size_t gi = (size_t)n * KP4 + c * 128 + (t >> 1);
            g_xq1[gi] = ph | (oh << 16);
            g_xq0[gi] = pl | (ol << 16);
        }
    }
    if (t == 0) {
        int h0, l0, h1, l1, h2, l2;
        qsplit(m0, inv, h0, l0); qsplit(m1m, inv, h1, l1); qsplit(m2m, inv, h2, l2);
        size_t gi = (size_t)n * KP4 + 1152;
        g_xq1[gi] = (uint32_t)(h0 & 0xFF) | ((uint32_t)(h1 & 0xFF) << 8) | ((uint32_t)(h2 & 0xFF) << 16);
        g_xq0[gi] = (uint32_t)(l0 & 0xFF) | ((uint32_t)(l1 & 0xFF) << 8) | ((uint32_t)(l2 & 0xFF) << 16);
    }
    if (t >= 1 && t < 8) {
        size_t gi = (size_t)n * KP4 + 1152 + t;
        g_xq1[gi] = 0; g_xq0[gi] = 0;
    }
}

// ---------- w1 scale + quantize ----------
__global__ __launch_bounds__(256) void wcolmax(const float* __restrict__ e_w1) {
    int t = threadIdx.x;
    int e = blockIdx.y, ks = blockIdx.z;
    int k0 = ks * 159, k1 = min(INDIM, k0 + 159);
    const float* W = e_w1 + (size_t)e * INDIM * HID + 4 * t;
    float m0 = 0.f, m1 = 0.f, m2 = 0.f, m3 = 0.f;
    #pragma unroll 4
    for (int k = k0; k < k1; k++) {
        float4 v = *(const float4*)(W + (size_t)k * HID);
        m0 = fmaxf(m0, fabsf(v.x)); m1 = fmaxf(m1, fabsf(v.y));
        m2 = fmaxf(m2, fabsf(v.z)); m3 = fmaxf(m3, fabsf(v.w));
    }
    int b = e * HID + 4 * t;
    atomicMax(&g_swmax[b + 0], __float_as_uint(m0));
    atomicMax(&g_swmax[b + 1], __float_as_uint(m1));
    atomicMax(&g_swmax[b + 2], __float_as_uint(m2));
    atomicMax(&g_swmax[b + 3], __float_as_uint(m3));
}
__global__ __launch_bounds__(256) void quant_w(const float* __restrict__ e_w1) {
    int t = threadIdx.x;
    int k4 = blockIdx.x, e = blockIdx.y;
    int nb = e * HID + 4 * t;
    uint4 mxu = *(const uint4*)&g_swmax[nb];
    float mx[4] = {fmaxf(__uint_as_float(mxu.x), 1e-20f),
                   fmaxf(__uint_as_float(mxu.y), 1e-20f),
                   fmaxf(__uint_as_float(mxu.z), 1e-20f),
                   fmaxf(__uint_as_float(mxu.w), 1e-20f)};
    float invq[4] = {QMAXF / mx[0], QMAXF / mx[1], QMAXF / mx[2], QMAXF / mx[3]};
    if (k4 == 0) {
        float4 sw = make_float4(mx[0] * (1.f / QMAXF), mx[1] * (1.f / QMAXF),
                                mx[2] * (1.f / QMAXF), mx[3] * (1.f / QMAXF));
        *(float4*)&g_sw[nb] = sw;
    }
    uint32_t hw[4] = {0, 0, 0, 0}, lw[4] = {0, 0, 0, 0};
    const float* W = e_w1 + (size_t)e * INDIM * HID + 4 * t;
    #pragma unroll
    for (int j = 0; j < 4; j++) {
        int k = 4 * k4 + j;
        float4 v = (k < INDIM) ? *(const float4*)(W + (size_t)k * HID)
                               : make_float4(0.f, 0.f, 0.f, 0.f);
        float vv[4] = {v.x, v.y, v.z, v.w};
        #pragma unroll
        for (int c = 0; c < 4; c++) {
            int h, l;
            qsplit(vv[c], invq[c], h, l);
            hw[c] |= (uint32_t)(h & 0xFF) << (8 * j);
            lw[c] |= (uint32_t)(l & 0xFF) << (8 * j);
        }
    }
    size_t idx = ((size_t)e * KP4 + k4) * HID + 4 * t;
    *(uint4*)&g_wq1[idx] = make_uint4(hw[0], hw[1], hw[2], hw[3]);
    *(uint4*)&g_wq0[idx] = make_uint4(lw[0], lw[1], lw[2], lw[3]);
}

// ---------- w2 scale + quantize ----------
__global__ __launch_bounds__(128) void wcolmax2(const float* __restrict__ e_w2) {
    int t = threadIdx.x;
    int e = blockIdx.y, ks = blockIdx.z;
    int k0 = ks * 64;
    const float* W = e_w2 + (size_t)e * HID * DMODEL + 4 * t;
    float m0 = 0.f, m1 = 0.f, m2 = 0.f, m3 = 0.f;
    #pragma unroll 4
    for (int k = k0; k < k0 + 64; k++) {
        float4 v = *(const float4*)(W + (size_t)k * DMODEL);
        m0 = fmaxf(m0, fabsf(v.x)); m1 = fmaxf(m1, fabsf(v.y));
        m2 = fmaxf(m2, fabsf(v.z)); m3 = fmaxf(m3, fabsf(v.w));
    }
    int b = e * DMODEL + 4 * t;
    atomicMax(&g_sw2max[b + 0], __float_as_uint(m0));
    atomicMax(&g_sw2max[b + 1], __float_as_uint(m1));
    atomicMax(&g_sw2max[b + 2], __float_as_uint(m2));
    atomicMax(&g_sw2max[b + 3], __float_as_uint(m3));
}
__global__ __launch_bounds__(128) void quant_w2(const float* __restrict__ e_w2) {
    int t = threadIdx.x;
    int k4 = blockIdx.x, e = blockIdx.y;
    int nb = e * DMODEL + 4 * t;
    uint4 mxu = *(const uint4*)&g_sw2max[nb];
    float mx[4] = {fmaxf(__uint_as_float(mxu.x), 1e-20f),
                   fmaxf(__uint_as_float(mxu.y), 1e-20f),
                   fmaxf(__uint_as_float(mxu.z), 1e-20f),
                   fmaxf(__uint_as_float(mxu.w), 1e-20f)};
    float invq[4] = {QMAXF / mx[0], QMAXF / mx[1], QMAXF / mx[2], QMAXF / mx[3]};
    if (k4 == 0) {
        float4 sw = make_float4(mx[0] * (1.f / QMAXF), mx[1] * (1.f / QMAXF),
                                mx[2] * (1.f / QMAXF), mx[3] * (1.f / QMAXF));
        *(float4*)&g_sw2[nb] = sw;
    }
    uint32_t hw[4] = {0, 0, 0, 0}, lw[4] = {0, 0, 0, 0};
    const float* W = e_w2 + (size_t)e * HID * DMODEL + 4 * t;
    #pragma unroll
    for (int j = 0; j < 4; j++) {
        float4 v = *(const float4*)(W + (size_t)(4 * k4 + j) * DMODEL);
        float vv[4] = {v.x, v.y, v.z, v.w};
        #pragma unroll
        for (int c = 0; c < 4; c++) {
            int h, l;
            qsplit(vv[c], invq[c], h, l);
            hw[c] |= (uint32_t)(h & 0xFF) << (8 * j);
            lw[c] |= (uint32_t)(l & 0xFF) << (8 * j);
        }
    }
    size_t idx = ((size_t)e * KP4H + k4) * DMODEL + 4 * t;
    *(uint4*)&g_w2q1[idx] = make_uint4(hw[0], hw[1], hw[2], hw[3]);
    *(uint4*)&g_w2q0[idx] = make_uint4(lw[0], lw[1], lw[2], lw[3]);
}

// ---------- eh rowmax + quantize ----------
__global__ __launch_bounds__(256) void quant_eh()
{
    int r = blockIdx.x, t = threadIdx.x;
    __shared__ float red[8];
    const float* ep = g_eh + (size_t)r * HID;
    float4 v = *(const float4*)(ep + 4 * t);
    float mx = fmaxf(fmaxf(fabsf(v.x), fabsf(v.y)), fmaxf(fabsf(v.z), fabsf(v.w)));
    #pragma unroll
    for (int o = 16; o; o >>= 1) mx = fmaxf(mx, __shfl_xor_sync(0xffffffffu, mx, o));
    if ((t & 31) == 0) red[t >> 5] = mx;
    __syncthreads();
    if (t == 0) {
        float m = red[0];
        #pragma unroll
        for (int i = 1; i < 8; i++) m = fmaxf(m, red[i]);
        red[0] = fmaxf(m, 1e-20f);
        g_seh[r] = red[0] * (1.f / QMAXF);
    }
    __syncthreads();
    float inv = QMAXF / red[0];
    float vv[4] = {v.x, v.y, v.z, v.w};
    uint32_t hw = 0, lw = 0;
    #pragma unroll
    for (int j = 0; j < 4; j++) {
        int h, l;
        qsplit(vv[j], inv, h, l);
        hw |= (uint32_t)(h & 0xFF) << (8 * j);
        lw |= (uint32_t)(l & 0xFF) << (8 * j);
    }
    g_ehq1[(size_t)r * KP4H + t] = hw;
    g_ehq0[(size_t)r * KP4H + t] = lw;
}

// ---------- dp4a GEMM core: MODE 1 = fc1, MODE 2 = fc2 ----------------------
template<int MODE>
__global__ __launch_bounds__(256, 2) void dp4a_fc(const float* __restrict__ bias)
{
    constexpr int BN  = (MODE == 1) ? HID : DMODEL;
    constexpr int KPX = (MODE == 1) ? KP4 : KP4H;
    __shared__ uint32_t As[2][2][8][128];
    __shared__ uint32_t Bs[3][2][8][64];
    __shared__ int   rt_s[128];
    __shared__ float sa_s[128];
    __shared__ int   slot_s[128];
    __shared__ float gw_s[128];

    int e = blockIdx.z;
    int m_base = g_off[e];
    int M = g_off[e + 1] - m_base;
    int mt = blockIdx.y * 128;
    if (mt >= M) return;
    int Mblk = min(128, M - mt);
    int nt = blockIdx.x * 64;
    int t = threadIdx.x;

    if (t < 128) {
        int mm = mt + t;
        int rr = m_base + ((mm < M) ? mm : 0);
        if (MODE == 1) {
            int tok = g_rows_token[rr];
            rt_s[t] = tok;
            sa_s[t] = g_sa[tok];
        } else {
            rt_s[t] = g_rows_token[rr];
            slot_s[t] = g_rows_slot[rr];
            gw_s[t] = g_rows_w[rr];
            sa_s[t] = g_seh[rr];
        }
    }
    __syncthreads();

    int ar = t >> 1, kh = (t & 1) * 4;
    const uint32_t* a1p;
    const uint32_t* a0p;
    if (MODE == 1) {
        a1p = g_xq1 + (size_t)rt_s[ar] * KPX + kh;
        a0p = g_xq0 + (size_t)rt_s[ar] * KPX + kh;
    } else {
        int rg = m_base + (((mt + ar) < M) ? (mt + ar) : 0);
        a1p = g_ehq1 + (size_t)rg * KPX + kh;
        a0p = g_ehq0 + (size_t)rg * KPX + kh;
    }

    int bl = t >> 7, bi_ = t & 127;
    int bk4 = bi_ >> 4, bn4 = (bi_ & 15) * 4;
    const uint32_t* bp;
    if (MODE == 1)
        bp = (bl ? g_wq1 : g_wq0) + ((size_t)e * KPX + bk4) * BN + nt + bn4;
    else
        bp = (bl ? g_w2q1 : g_w2q0) + ((size_t)e * KPX + bk4) * BN + nt + bn4;
    uint32_t bDst = smem_u32(&Bs[0][bl][bk4][bn4]);

    int tx = t & 15, ty = t >> 4;
    int P11[8][4], Pm[8][4];
    #pragma unroll
    for (int i = 0; i < 8; i++)
        #pragma unroll
        for (int j = 0; j < 4; j++) { P11[i][j] = 0; Pm[i][j] = 0; }

    uint4 aR1, aR0;
    aR1 = *(const uint4*)a1p;
    aR0 = *(const uint4*)a0p;
    cp16(bDst, bp);
    CP_COMMIT();
    {
        uint32_t v1[4] = {aR1.x, aR1.y, aR1.z, aR1.w};
        uint32_t v0[4] = {aR0.x, aR0.y, aR0.z, aR0.w};
        #pragma unroll
        for (int j = 0; j < 4; j++) { As[0][1][kh + j][ar] = v1[j]; As[0][0][kh + j][ar] = v0[j]; }
    }
    aR1 = *(const uint4*)(a1p + 8);
    aR0 = *(const uint4*)(a0p + 8);
    cp16(bDst + 4096u, bp + 8 * BN);
    CP_COMMIT();

    const int NSTG = KPX / 8;
    #pragma unroll 1
    for (int s = 0; s < NSTG; s++) {
        CP_WAIT(1);
        __syncthreads();
        int ab = s & 1, bb = s % 3;

        #pragma unroll
        for (int k4 = 0; k4 < 8; k4++) {
            uint4 f1a = *(const uint4*)&As[ab][1][k4][ty * 8];
            uint4 f1b = *(const uint4*)&As[ab][1][k4][ty * 8 + 4];
            uint4 f0a = *(const uint4*)&As[ab][0][k4][ty * 8];
            uint4 f0b = *(const uint4*)&As[ab][0][k4][ty * 8 + 4];
            uint4 bw1 = *(const uint4*)&Bs[bb][1][k4][tx * 4];
            uint4 bw0 = *(const uint4*)&Bs[bb][0][k4][tx * 4];
            uint32_t a1v[8] = {f1a.x, f1a.y, f1a.z, f1a.w, f1b.x, f1b.y, f1b.z, f1b.w};
            uint32_t a0v[8] = {f0a.x, f0a.y, f0a.z, f0a.w, f0b.x, f0b.y, f0b.z, f0b.w};
            uint32_t b1v[4] = {bw1.x, bw1.y, bw1.z, bw1.w};
            uint32_t b0v[4] = {bw0.x, bw0.y, bw0.z, bw0.w};
            #pragma unroll
            for (int i = 0; i < 8; i++)
                #pragma unroll
                for (int j = 0; j < 4; j++) {
                    P11[i][j] = __dp4a((int)a1v[i], (int)b1v[j], P11[i][j]);
                    Pm[i][j]  = __dp4a((int)a1v[i], (int)b0v[j], Pm[i][j]);
                    Pm[i][j]  = __dp4a((int)a0v[i], (int)b1v[j], Pm[i][j]);
                }
        }

        if (s + 1 < NSTG) {
            int nb = (s + 1) & 1;
            uint32_t v1[4] = {aR1.x, aR1.y, aR1.z, aR1.w};
            uint32_t v0[4] = {aR0.x, aR0.y, aR0.z, aR0.w};
            #pragma unroll
            for (int j = 0; j < 4; j++) { As[nb][1][kh + j][ar] = v1[j]; As[nb][0][kh + j][ar] = v0[j]; }
        }
        if (s + 2 < NSTG) {
            int s2 = s + 2;
            aR1 = *(const uint4*)(a1p + s2 * 8);
            aR0 = *(const uint4*)(a0p + s2 * 8);
            cp16(bDst + (uint32_t)(s2 % 3) * 4096u, bp + (size_t)s2 * 8 * BN);
        }
        CP_COMMIT();
    }

    float4 bv = *(const float4*)(bias + (size_t)e * BN + nt + tx * 4);
    const float* swp = ((MODE == 1) ? g_sw : g_sw2) + (size_t)e * BN + nt + tx * 4;
    float sw0 = swp[0], sw1 = swp[1], sw2 = swp[2], sw3 = swp[3];

    #pragma unroll
    for (int i = 0; i < 8; i++) {
        int r = ty * 8 + i;
        if (r >= Mblk) continue;
        float sa = sa_s[r];
        float c0 = sa * sw0 * (16384.f * (float)P11[i][0] + 128.f * (float)Pm[i][0]) + bv.x;
        float c1 = sa * sw1 * (16384.f * (float)P11[i][1] + 128.f * (float)Pm[i][1]) + bv.y;
        float c2 = sa * sw2 * (16384.f * (float)P11[i][2] + 128.f * (float)Pm[i][2]) + bv.z;
        float c3 = sa * sw3 * (16384.f * (float)P11[i][3] + 128.f * (float)Pm[i][3]) + bv.w;
        if (MODE == 1) {
            float4 o = make_float4(gelu_f(c0), gelu_f(c1), gelu_f(c2), gelu_f(c3));
            *(float4*)(g_eh + (size_t)(m_base + mt + r) * HID + nt + tx * 4) = o;
        } else {
            int token = rt_s[r];
            int slot  = slot_s[r];
            float gw  = gw_s[r];
            float4 o = make_float4(c0 * gw, c1 * gw, c2 * gw, c3 * gw);
            *(float4*)(g_outs + ((size_t)token * 2 + slot) * DMODEL + nt + tx * 4) = o;
        }
    }
}

// ---------- FFMA router fc1 ----------
__global__ __launch_bounds__(256) void ffma_router(const float* __restrict__ W,
                                                   const float* __restrict__ bias)
{
    const int BN = RHID, NS = XLD / TK;
    int mt = blockIdx.y * TM;
    int nt = blockIdx.x * TN;

    extern __shared__ char smem[];
    uint32_t sb = smem_u32(smem);
    u64*      Adup = (u64*)smem;
    uint32_t* Bsm  = (uint32_t*)(smem + SM_B0);

    int t = threadIdx.x;
    int ar = t >> 1, kh = (t & 1) * 8;
    const float* aRow = g_x + (size_t)(mt + ar) * XLD + kh;
    int bkr = t >> 4, bch = (t & 15) * 4;
    const float* bRow = W + (size_t)bkr * BN + nt + bch;
    uint32_t bDstBase = sb + SM_B0 + (uint32_t)(bkr * TN + bch) * 4u;

    int tx = t & 15, ty = t >> 4;
    u64 acc[8][2];
    #pragma unroll
    for (int i = 0; i < 8; i++) { acc[i][0] = 0ull; acc[i][1] = 0ull; }

    float4 aR0, aR1;
    aR0 = *(const float4*)(aRow);
    aR1 = *(const float4*)(aRow + 4);
    cp16sz(bDstBase, (bkr < INDIM) ? bRow : W, (bkr < INDIM) ? 16u : 0u);
    CP_COMMIT();
    {
        float v[8] = {aR0.x, aR0.y, aR0.z, aR0.w, aR1.x, aR1.y, aR1.z, aR1.w};
        #pragma unroll
        for (int i = 0; i < 8; i++) { u64 d; PACKDUP(d, v[i]); Adup[(kh + i) * TM + ar] = d; }
    }
    aR0 = *(const float4*)(aRow + TK);
    aR1 = *(const float4*)(aRow + TK + 4);
    {
        int kb = TK + bkr;
        cp16sz(bDstBase + 4096u, (kb < INDIM) ? (bRow + (size_t)TK * BN) : W, (kb < INDIM) ? 16u : 0u);
    }
    CP_COMMIT();

    #pragma unroll 1
    for (int s = 0; s < NS; s++) {
        CP_WAIT(1);
        __syncthreads();
        const u64* Ad = Adup + (size_t)(s & 1) * (TK * TM);
        const uint32_t* Bb = Bsm + (size_t)(s % 3) * (TK * TN);

        #pragma unroll
        for (int k = 0; k < TK; k++) {
            u64 af[8];
            #pragma unroll
            for (int i = 0; i < 4; i++)
                *(ulonglong2*)&af[2 * i] = *(const ulonglong2*)&Ad[k * TM + ty * 8 + 2 * i];
            ulonglong2 bf = *(const ulonglong2*)&Bb[k * TN + tx * 4];
            #pragma unroll
            for (int i = 0; i < 8; i++) {
                FMA2(acc[i][0], af[i], bf.x);
                FMA2(acc[i][1], af[i], bf.y);
            }
        }

        if (s + 1 < NS) {
            u64* Aw = Adup + (size_t)((s + 1) & 1) * (TK * TM);
            float v[8] = {aR0.x, aR0.y, aR0.z, aR0.w, aR1.x, aR1.y, aR1.z, aR1.w};
            #pragma unroll
            for (int i = 0; i < 8; i++) { u64 d; PACKDUP(d, v[i]); Aw[(kh + i) * TM + ar] = d; }
        }
        if (s + 2 < NS) {
            int s2 = s + 2;
            aR0 = *(const float4*)(aRow + s2 * TK);
            aR1 = *(const float4*)(aRow + s2 * TK + 4);
            int kb = s2 * TK + bkr;
            cp16sz(bDstBase + (uint32_t)(s2 % 3) * 4096u,
                   (kb < INDIM) ? (bRow + (size_t)s2 * TK * BN) : W, (kb < INDIM) ? 16u : 0u);
        }
        CP_COMMIT();
    }

    float4 bv = *(const float4*)(bias + nt + tx * 4);
    #pragma unroll
    for (int i = 0; i < 8; i++) {
        int rloc = ty * 8 + i;
        float c0, c1, c2, c3;
        UNPACK2(c0, c1, acc[i][0]);
        UNPACK2(c2, c3, acc[i][1]);
        float4 o = make_float4(gelu_f(c0 + bv.x), gelu_f(c1 + bv.y),
                               gelu_f(c2 + bv.z), gelu_f(c3 + bv.w));
        *(float4*)(g_rh + (size_t)(mt + rloc) * RHID + nt + tx * 4) = o;
    }
}

// ---------- router head: one warp per token (coalesced) ----------
__global__ __launch_bounds__(256) void router_head(
    const float* __restrict__ r_w2, const float* __restrict__ r_b2,
    const float* __restrict__ log_temp)
{
    __shared__ float w2s[RHID * NEXP];
    __shared__ float b2s[NEXP];
    int t = threadIdx.x;
    for (int i = t; i < RHID * NEXP; i += 256) w2s[i] = r_w2[i];
    if (t < NEXP) b2s[t] = r_b2[t];
    __syncthreads();

    int w = t >> 5, lane = t & 31;
    int n = blockIdx.x * 8 + w;
    const float* rhp = g_rh + (size_t)n * RHID;

    float acc[NEXP];
    #pragma unroll
    for (int e = 0; e < NEXP; e++) acc[e] = 0.f;
    #pragma unroll
    for (int c = 0; c < 8; c++) {
        int k = c * 32 + lane;
        float rv = rhp[k];
        const float* wp = &w2s[k * NEXP];
        #pragma unroll
        for (int e = 0; e < NEXP; e++) acc[e] = fmaf(rv, wp[e], acc[e]);
    }
    #pragma unroll
    for (int e = 0; e < NEXP; e++)
        #pragma unroll
        for (int o = 16; o; o >>= 1)
            acc[e] += __shfl_xor_sync(0xffffffffu, acc[e], o);

    if (lane == 0) {
        float temp = expf(*log_temp);
        temp = fminf(fmaxf(temp, 1e-3f), 100.f);
        float inv_t = 1.f / temp;
        #pragma unroll
        for (int e = 0; e < NEXP; e++) acc[e] = (acc[e] + b2s[e]) * inv_t;

        int i0 = 0;
        #pragma unroll
        for (int e = 1; e < NEXP; e++) if (acc[e] > acc[i0]) i0 = e;
        int i1 = (i0 == 0) ? 1 : 0;
        #pragma unroll
        for (int e = 0; e < NEXP; e++)
            if (e != i0 && acc[e] > acc[i1]) i1 = e;

        float e1 = expf(acc[i1] - acc[i0]);
        float inv_s = 1.f / (1.f + e1);
        g_topi[n * 2 + 0] = i0; g_topw[n * 2 + 0] = inv_s;
        g_topi[n * 2 + 1] = i1; g_topw[n * 2 + 1] = e1 * inv_s;
        atomicAdd(&g_cnt[i0], 1);
        atomicAdd(&g_cnt[i1], 1);
    }
}

// ---------- bookkeeping ----------
__global__ __launch_bounds__(256) void zero_all() {
    int i = blockIdx.x * 256 + threadIdx.x;
    if (i < NEXP * HID) g_swmax[i] = 0u;
    if (i < NEXP * DMODEL) g_sw2max[i] = 0u;
    if (i < NEXP) { g_cnt[i] = 0; g_cursor[i] = 0; }
}
__global__ void calc_offsets() {
    if (threadIdx.x == 0) {
        int s = 0;
        for (int e = 0; e < NEXP; e++) { g_off[e] = s; s += g_cnt[e]; }
        g_off[NEXP] = s;
    }
}
__global__ __launch_bounds__(256) void scatter_rows() {
    int n = blockIdx.x * 256 + threadIdx.x;
    if (n >= N_TOK) return;
    #pragma unroll
    for (int k = 0; k < 2; k++) {
        int e = g_topi[n * 2 + k];
        int pos = atomicAdd(&g_cursor[e], 1);
        int r = g_off[e] + pos;
        g_rows_token[r] = n;
        g_rows_slot[r] = k;
        g_rows_w[r] = g_topw[n * 2 + k];
    }
}

// ---------- combine + final LN ----------
__global__ __launch_bounds__(256) void combine_ln(
    const float* __restrict__ oln_g, const float* __restrict__ oln_b,
    float* __restrict__ out)
{
    int n = blockIdx.x, t = threadIdx.x, t1 = t + 256;
    __shared__ float red[16];
    size_t b0 = (size_t)(n * 2) * DMODEL, b1 = b0 + DMODEL, bz = (size_t)n * DMODEL;
    float v0 = g_outs[b0 + t]  + g_outs[b1 + t]  + g_zres[bz + t];
    float v1 = g_outs[b0 + t1] + g_outs[b1 + t1] + g_zres[bz + t1];
    float v2[2] = {v0 + v1, v0 * v0 + v1 * v1};
    blockReduceV<2>(v2, red);
    float m = v2[0] * (1.f / DMODEL);
    float rs = rsqrtf(v2[1] * (1.f / DMODEL) - m * m + LN_EPS);
    out[bz + t]  = (v0 - m) * rs * oln_g[t]  + oln_b[t];
    out[bz + t1] = (v1 - m) * rs * oln_g[t1] + oln_b[t1];
}

// ---------- launch ----------
extern "C" void kernel_launch(void* const* d_in, const int* in_sizes, int n_in,
                              void* d_out, int out_size)
{
    const float* z1    = (const float*)d_in[0];
    const float* z2    = (const float*)d_in[1];
    const float* z3    = (const float*)d_in[2];
    const float* mask  = (const float*)d_in[3];
    const float* ln_g  = (const float*)d_in[4];
    const float* ln_b  = (const float*)d_in[5];
    const float* lnp_g = (const float*)d_in[6];
    const float* lnp_b = (const float*)d_in[7];
    const float* oln_g = (const float*)d_in[8];
    const float* oln_b = (const float*)d_in[9];
    const float* r_w1  = (const float*)d_in[10];
    const float* r_b1  = (const float*)d_in[11];
    const float* r_w2  = (const float*)d_in[12];
    const float* r_b2  = (const float*)d_in[13];
    const float* log_temp = (const float*)d_in[14];
    const float* e_w1  = (const float*)d_in[15];
    const float* e_b1  = (const float*)d_in[16];
    const float* e_w2  = (const float*)d_in[17];
    const float* e_b2  = (const float*)d_in[18];
    float* out = (float*)d_out;

    zero_all<<<(NEXP * HID + 255) / 256, 256>>>();
    build_x_kernel<<<N_TOK, 256>>>(z1, z2, z3, mask, ln_g, ln_b, lnp_g, lnp_b);

    wcolmax<<<dim3(1, NEXP, 29), 256>>>(e_w1);
    quant_w<<<dim3(KP4, NEXP), 256>>>(e_w1);
    wcolmax2<<<dim3(1, NEXP, 16), 128>>>(e_w2);
    quant_w2<<<dim3(KP4H, NEXP), 128>>>(e_w2);

    ffma_router<<<dim3(RHID / TN, N_TOK / TM, 1), 256, SMEM_TOTAL>>>(r_w1, r_b1);
    router_head<<<N_TOK / 8, 256>>>(r_w2, r_b2, log_temp);
    calc_offsets<<<1, 32>>>();
    scatter_rows<<<N_TOK / 256, 256>>>();

    dp4a_fc<1><<<dim3(HID / 64, NROWS / 128, NEXP), 256>>>(e_b1);
    quant_eh<<<NROWS, 256>>>();
    dp4a_fc<2><<<dim3(DMODEL / 64, NROWS / 128, NEXP), 256>>>(e_b2);

    combine_ln<<<N_TOK, 256>>>(oln_g, oln_b, out);
}